// round 12
// baseline (speedup 1.0000x reference)
#include <cuda_runtime.h>
#include <cstdint>

#define B_DIM 8192
#define D_DIM 768
#define L_DIM 16384
#define K_TOP 100
#define DELTA_BAND 2.5e-3f
#define UNC_CAP 192
#define CAND_CAP 512
#define TH_CAND 2.15f

// ============================ device scratch ============================
__device__ float g_Af[(size_t)B_DIM * D_DIM];   // A, MMA-fragment order
__device__ float g_Wf[(size_t)D_DIM * L_DIM];   // W_enc tf32, MMA-fragment order
__device__ float g_Xb[(size_t)B_DIM * D_DIM];   // exact fp32 (xn - pre_bias), row-major
__device__ float g_WT[(size_t)L_DIM * D_DIM];   // W_enc exact transpose, [L][D]
__device__ float g_mu[B_DIM];
__device__ float g_std[B_DIM];
__device__ int   g_tidx[B_DIM * K_TOP];
__device__ float g_tval[B_DIM * K_TOP];

// ============================ helpers ============================
__device__ __forceinline__ uint32_t smem_to_u32(const void* p) {
    uint32_t a;
    asm("{ .reg .u64 t; cvta.to.shared.u64 t, %1; cvt.u32.u64 %0, t; }" : "=r"(a) : "l"(p));
    return a;
}
__device__ __forceinline__ float tf32r(float x) {
    uint32_t u;
    asm("cvt.rna.tf32.f32 %0, %1;" : "=r"(u) : "f"(x));
    return __uint_as_float(u);
}
__device__ __forceinline__ void cp16(uint32_t saddr, const void* g) {
    asm volatile("cp.async.cg.shared.global [%0], [%1], 16;" :: "r"(saddr), "l"(g));
}
#define CP_COMMIT() asm volatile("cp.async.commit_group;" ::: "memory")
#define CP_WAIT0()  asm volatile("cp.async.wait_group 0;" ::: "memory")

__device__ __forceinline__ void mma_tf32(float* d, const uint32_t* a, const uint32_t* b) {
    asm volatile(
        "mma.sync.aligned.m16n8k8.row.col.f32.tf32.tf32.f32 "
        "{%0,%1,%2,%3}, {%4,%5,%6,%7}, {%8,%9}, {%0,%1,%2,%3};"
        : "+f"(d[0]), "+f"(d[1]), "+f"(d[2]), "+f"(d[3])
        : "r"(a[0]), "r"(a[1]), "r"(a[2]), "r"(a[3]), "r"(b[0]), "r"(b[1]));
}

__device__ __forceinline__ float key_to_float(uint32_t k) {
    uint32_t u = (k & 0x80000000u) ? (k & 0x7FFFFFFFu) : ~k;
    return __uint_as_float(u);
}
__device__ __forceinline__ uint32_t float_to_key(float f) {
    uint32_t u = __float_as_uint(f);
    return (u & 0x80000000u) ? ~u : (u | 0x80000000u);
}

// ============================ kernel 1: fused prep ============================
#define WP_KT (D_DIM / 32)        // 24
#define WP_NT (L_DIM / 256)       // 64
#define WP_BLOCKS (WP_KT * WP_NT) // 1536

__global__ void __launch_bounds__(256) prep_kernel(const float* __restrict__ x,
                                                   const float* __restrict__ pre_bias,
                                                   const float* __restrict__ W) {
    __shared__ float sw[32 * 257];
    __shared__ float rs[8], rs2[8], bc[2];
    int bid = blockIdx.x, t = threadIdx.x;

    if (bid < B_DIM) {
        int row = bid;
        const float* xr = x + (size_t)row * D_DIM;
        float v0 = xr[t], v1 = xr[t + 256], v2 = xr[t + 512];
        float s = v0 + v1 + v2;
        float s2 = v0 * v0 + v1 * v1 + v2 * v2;
        for (int o = 16; o; o >>= 1) {
            s  += __shfl_down_sync(0xFFFFFFFFu, s,  o);
            s2 += __shfl_down_sync(0xFFFFFFFFu, s2, o);
        }
        if ((t & 31) == 0) { rs[t >> 5] = s; rs2[t >> 5] = s2; }
        __syncthreads();
        if (t == 0) {
            float a = 0.f, b = 0.f;
            for (int w = 0; w < 8; w++) { a += rs[w]; b += rs2[w]; }
            float mu = a / (float)D_DIM;
            float var = b / (float)D_DIM - mu * mu;
            float sd = sqrtf(fmaxf(var, 0.0f));
            bc[0] = mu; bc[1] = sd;
            g_mu[row] = mu; g_std[row] = sd;
        }
        __syncthreads();
        float mu = bc[0], sd = bc[1];
        float inv = 1.0f / (sd + 1e-5f);
        int p = row >> 7, rloc = row & 127;
        int mb = rloc >> 4, r4 = rloc & 7, hi = (rloc >> 3) & 1;
        size_t pbase = ((size_t)p * 96) * 1024 + (size_t)mb * 128 + (size_t)r4 * 16 + hi;
        float* Xr = g_Xb + (size_t)row * D_DIM;
        #pragma unroll
        for (int j = 0; j < 3; j++) {
            int k = t + j * 256;
            float v = (j == 0 ? v0 : (j == 1 ? v1 : v2));
            float e = (v - mu) * inv - pre_bias[k];
            Xr[k] = e;
            int oct = k >> 3, kl = k & 7, cs = kl & 3, khi = kl >> 2;
            g_Af[pbase + (size_t)oct * 1024 + cs * 4 + 2 * khi] = tf32r(e);
        }
    } else {
        int wb = bid - B_DIM;
        int kt = wb % WP_KT, nt = wb / WP_KT;
        int k0 = kt * 32, n0 = nt * 256;

        #pragma unroll 8
        for (int r = 0; r < 32; r++)
            sw[r * 257 + t] = W[(size_t)(k0 + r) * L_DIM + n0 + t];
        __syncthreads();

        {
            int wrp = t >> 5, ln = t & 31;
            #pragma unroll 8
            for (int i = 0; i < 32; i++) {
                int lcol = wrp * 32 + i;
                g_WT[(size_t)(n0 + lcol) * D_DIM + k0 + ln] = sw[ln * 257 + lcol];
            }
        }

        #pragma unroll
        for (int ol = 0; ol < 4; ol++) {
            int oct = (k0 >> 3) + ol;
            float* out = g_Wf + ((size_t)oct * 2048 + (size_t)nt * 32) * 64;
            #pragma unroll
            for (int j = 0; j < 4; j++) {
                int pr = t * 4 + j;
                int nb8l = pr >> 5, r4 = (pr >> 2) & 7, cs = pr & 3;
                int n = nb8l * 8 + r4;
                out[pr * 2 + 0] = tf32r(sw[(ol * 8 + cs) * 257 + n]);
                out[pr * 2 + 1] = tf32r(sw[(ol * 8 + cs + 4) * 257 + n]);
            }
        }
    }
}

// ============================ kernel 3: encode GEMM (tf32 mma, KC=64, 2x96KB stages) ============================
#define KC 64
#define NCHUNK (D_DIM / KC)
#define STAGE_BYTES 98304
#define B_IN_STAGE 32768
#define GEMM_SMEM (2 * STAGE_BYTES)

__global__ void __launch_bounds__(256, 1) gemm_kernel(const float* __restrict__ lat_bias,
                                                      float* __restrict__ C) {
    extern __shared__ char smem[];
    uint32_t sb = smem_to_u32(smem);
    int t = threadIdx.x, wid = t >> 5, lane = t & 31;
    int wm = wid & 1, wn = wid >> 1;
    int r4 = lane >> 2, cs = lane & 3;
    int m0 = blockIdx.y * 128, n0 = blockIdx.x * 256;
    int panel = m0 >> 7, nb0 = n0 >> 3;

    auto issue = [&](int c, int slot) {
        uint32_t dst = sb + slot * STAGE_BYTES;
        const float* Asrc = g_Af + ((size_t)panel * 96 + c * 8) * 1024;
        #pragma unroll
        for (int i = 0; i < 8; i++) {
            int idx = t + i * 256;
            cp16(dst + idx * 16, Asrc + idx * 4);
        }
        #pragma unroll
        for (int j = 0; j < 8; j++) {
            const float* Bsrc = g_Wf + ((size_t)(c * 8 + j) * 2048 + nb0) * 64;
            #pragma unroll
            for (int i = 0; i < 2; i++) {
                int idx = t + i * 256;
                cp16(dst + B_IN_STAGE + j * 8192 + idx * 16, Bsrc + idx * 4);
            }
        }
    };

    auto loadFrags = [&](int slot, int k8, uint32_t a[4][4], uint32_t b[8][2]) {
        const float4* Aq = (const float4*)(smem + slot * STAGE_BYTES);
        const float2* Bp = (const float2*)(smem + slot * STAGE_BYTES + B_IN_STAGE);
        #pragma unroll
        for (int mt = 0; mt < 4; mt++) {
            float4 q = Aq[k8 * 256 + (wm * 4 + mt) * 32 + lane];
            a[mt][0] = __float_as_uint(q.x); a[mt][1] = __float_as_uint(q.y);
            a[mt][2] = __float_as_uint(q.z); a[mt][3] = __float_as_uint(q.w);
        }
        #pragma unroll
        for (int nt = 0; nt < 8; nt++) {
            float2 p2 = Bp[k8 * 1024 + (wn * 8 + nt) * 32 + lane];
            b[nt][0] = __float_as_uint(p2.x); b[nt][1] = __float_as_uint(p2.y);
        }
    };

    float acc[4][8][4];
    #pragma unroll
    for (int mt = 0; mt < 4; mt++)
        #pragma unroll
        for (int nt = 0; nt < 8; nt++)
            #pragma unroll
            for (int q = 0; q < 4; q++) acc[mt][nt][q] = 0.f;

    uint32_t aF[2][4][4], bF[2][8][2];

    issue(0, 0); CP_COMMIT();
    CP_WAIT0();
    __syncthreads();
    loadFrags(0, 0, aF[0], bF[0]);

    int pp = 0;
    for (int c = 0; c < NCHUNK; c++) {
        if (c + 1 < NCHUNK) { issue(c + 1, (c + 1) & 1); CP_COMMIT(); }
        int slot = c & 1;
        #pragma unroll
        for (int k8 = 0; k8 < 8; k8++) {
            int nxt = pp ^ 1;
            if (k8 < 7) {
                loadFrags(slot, k8 + 1, aF[nxt], bF[nxt]);
            } else if (c + 1 < NCHUNK) {
                CP_WAIT0();
                __syncthreads();
                loadFrags((c + 1) & 1, 0, aF[nxt], bF[nxt]);
            }
            #pragma unroll
            for (int mt = 0; mt < 4; mt++)
                #pragma unroll
                for (int nt = 0; nt < 8; nt++)
                    mma_tf32(acc[mt][nt], aF[pp][mt], bF[pp][nt]);
            pp ^= 1;
        }
    }

    #pragma unroll
    for (int mt = 0; mt < 4; mt++) {
        int m = m0 + wm * 64 + mt * 16 + r4;
        #pragma unroll
        for (int nt = 0; nt < 8; nt++) {
            int n = n0 + wn * 64 + nt * 8 + cs * 2;
            float2 bb = *(const float2*)(lat_bias + n);
            float2 v0 = make_float2(acc[mt][nt][0] + bb.x, acc[mt][nt][1] + bb.y);
            float2 v1 = make_float2(acc[mt][nt][2] + bb.x, acc[mt][nt][3] + bb.y);
            *(float2*)(C + (size_t)m * L_DIM + n) = v0;
            *(float2*)(C + (size_t)(m + 8) * L_DIM + n) = v1;
        }
    }
}

// ============================ kernel 4: single-pass streaming top-k ============================
__global__ void __launch_bounds__(256) topk_kernel(const float* __restrict__ P,
                                                   const float* __restrict__ lat_bias,
                                                   float* __restrict__ latents) {
    __shared__ int   s_redi[8];
    __shared__ int   s_total;
    __shared__ int   s_cnt;
    __shared__ uint32_t srt_key[CAND_CAP];
    __shared__ int      srt_idx[CAND_CAP];
    __shared__ int      unc_ix[UNC_CAP];
    __shared__ float    unc_ex[UNC_CAP];
    __shared__ int      fin_idx[K_TOP];
    __shared__ float    fin_val[K_TOP];

    int row = blockIdx.x, t = threadIdx.x, lane = t & 31, wid = t >> 5;
    const float* Pr = P + (size_t)row * L_DIM;

    // ---- pass 1: stream the row once; push (key,idx) of values > TH_CAND ----
    if (t == 0) s_cnt = 0;
    __syncthreads();
    #pragma unroll 4
    for (int i = 0; i < 64; i++) {
        int idx = t + (i << 8);
        float v = Pr[idx];
        bool p = (v > TH_CAND);
        unsigned m = __ballot_sync(0xFFFFFFFFu, p);
        if (m) {
            int ldr = __ffs(m) - 1;
            int base = 0;
            if (lane == ldr) base = atomicAdd(&s_cnt, __popc(m));
            base = __shfl_sync(0xFFFFFFFFu, base, ldr);
            if (p) {
                int slot = base + __popc(m & ((1u << lane) - 1u));
                if (slot < CAND_CAP) { srt_key[slot] = float_to_key(v); srt_idx[slot] = idx; }
            }
        }
    }
    __syncthreads();
    int cnt = s_cnt;                            // block-uniform
    int mode = (cnt >= K_TOP && cnt <= CAND_CAP) ? 0 : 1;
    uint32_t T16 = 0;
    int have_T16 = 0;
    uint32_t klo = 0, khi = 0;

    for (int attempt = 0; attempt < 4; attempt++) {
        if (mode == 1) {
            // rare fallback: exact 16-bit-threshold scan from gmem (row is L2-hot)
            if (!have_T16) {
                uint32_t lo = 0, hi = 0xFFFFu;
                while (lo < hi) {
                    uint32_t mid = lo + (hi - lo + 1) / 2;
                    int local = 0;
                    for (int i = 0; i < 64; i++)
                        local += (int)((float_to_key(Pr[t + (i << 8)]) >> 16) >= mid);
                    for (int o = 16; o; o >>= 1) local += __shfl_down_sync(0xFFFFFFFFu, local, o);
                    if (lane == 0) s_redi[wid] = local;
                    __syncthreads();
                    if (t == 0) { int tot = 0; for (int w = 0; w < 8; w++) tot += s_redi[w]; s_total = tot; }
                    __syncthreads();
                    int total = s_total;
                    __syncthreads();
                    if (total >= K_TOP) lo = mid; else hi = mid - 1;
                }
                T16 = lo; have_T16 = 1;
            }
            if (t == 0) s_cnt = 0;
            __syncthreads();
            for (int i = 0; i < 64; i++) {
                int idx = t + (i << 8);
                uint32_t k = float_to_key(Pr[idx]);
                if ((k >> 16) >= T16) {
                    int p = atomicAdd(&s_cnt, 1);
                    if (p < CAND_CAP) { srt_key[p] = k; srt_idx[p] = idx; }
                }
            }
            __syncthreads();
            cnt = s_cnt < CAND_CAP ? s_cnt : CAND_CAP;
        }
        // pad unused slots
        for (int j = t; j < CAND_CAP; j += 256)
            if (j >= cnt) { srt_key[j] = 0u; srt_idx[j] = 0x7FFFFFFF; }
        __syncthreads();

        // ---- bitonic sort 512: (key desc, idx asc) ----
        for (int k2 = 2; k2 <= CAND_CAP; k2 <<= 1) {
            for (int j2 = k2 >> 1; j2 > 0; j2 >>= 1) {
                for (int i = t; i < CAND_CAP; i += 256) {
                    int ixj = i ^ j2;
                    if (ixj > i) {
                        uint32_t ki = srt_key[i], kj = srt_key[ixj];
                        int ii = srt_idx[i], ij = srt_idx[ixj];
                        bool gt = (ki > kj) || (ki == kj && ii < ij);
                        bool dir = ((i & k2) == 0);
                        if (dir ? !gt : gt) {
                            srt_key[i] = kj; srt_key[ixj] = ki;
                            srt_idx[i] = ij; srt_idx[ixj] = ii;
                        }
                    }
                }
                __syncthreads();
            }
        }

        float v100f = key_to_float(srt_key[K_TOP - 1]);
        klo = float_to_key(v100f - DELTA_BAND);
        khi = float_to_key(v100f + DELTA_BAND);
        if (mode == 0) {
            if (v100f - DELTA_BAND <= TH_CAND) { mode = 1; __syncthreads(); continue; }
            break;
        } else {
            if ((klo >> 16) >= T16 || T16 == 0) break;
            T16 = klo >> 16;
            __syncthreads();
        }
    }

    // ---- band boundaries ----
    {
        int l0 = 0, l1 = 0;
        for (int j = t; j < CAND_CAP; j += 256) {
            l0 += (int)(srt_key[j] > khi);
            l1 += (int)(srt_key[j] >= klo);
        }
        int v = l0;
        for (int o = 16; o; o >>= 1) v += __shfl_down_sync(0xFFFFFFFFu, v, o);
        if (lane == 0) s_redi[wid] = v;
        __syncthreads();
        if (t == 0) { int tot = 0; for (int w = 0; w < 8; w++) tot += s_redi[w]; s_total = tot; }
        __syncthreads();
        l0 = s_total;
        __syncthreads();
        v = l1;
        for (int o = 16; o; o >>= 1) v += __shfl_down_sync(0xFFFFFFFFu, v, o);
        if (lane == 0) s_redi[wid] = v;
        __syncthreads();
        if (t == 0) { int tot = 0; for (int w = 0; w < 8; w++) tot += s_redi[w]; s_total = tot; }
        __syncthreads();
        l1 = s_total;
        __syncthreads();
        if (t == 0) { s_redi[0] = l0; s_redi[1] = l1; }
        __syncthreads();
    }
    int j0 = s_redi[0];
    int j1 = s_redi[1];
    if (j0 > K_TOP - 1) j0 = K_TOP - 1;
    int U = j1 - j0; if (U > UNC_CAP) U = UNC_CAP;
    int need = K_TOP - j0;

    // ---- exact recompute for band members ----
    if (t < U) unc_ix[t] = srt_idx[j0 + t];
    __syncthreads();
    const float* Xr = g_Xb + (size_t)row * D_DIM;
    for (int q = wid; q < U; q += 8) {
        const float* w = g_WT + (size_t)unc_ix[q] * D_DIM;
        float s = 0.f, comp = 0.f;
        for (int d = lane; d < D_DIM; d += 32) {
            float prod = Xr[d] * w[d];
            float tn = s + prod;
            if (fabsf(s) >= fabsf(prod)) comp += (s - tn) + prod;
            else                         comp += (prod - tn) + s;
            s = tn;
        }
        s += comp;
        for (int o = 16; o; o >>= 1) s += __shfl_xor_sync(0xFFFFFFFFu, s, o);
        if (lane == 0) unc_ex[q] = s + lat_bias[unc_ix[q]];
    }
    __syncthreads();

    if (t < j0) { fin_idx[t] = srt_idx[t]; fin_val[t] = key_to_float(srt_key[t]); }
    __syncthreads();
    if (t == 0) {
        for (int a = 1; a < U; a++) {
            float vv = unc_ex[a]; int ii = unc_ix[a]; int b = a - 1;
            while (b >= 0 && (unc_ex[b] < vv || (unc_ex[b] == vv && unc_ix[b] > ii))) {
                unc_ex[b + 1] = unc_ex[b]; unc_ix[b + 1] = unc_ix[b]; b--;
            }
            unc_ex[b + 1] = vv; unc_ix[b + 1] = ii;
        }
        for (int q = 0; q < need; q++) {
            fin_idx[j0 + q] = unc_ix[q]; fin_val[j0 + q] = unc_ex[q];
        }
    }
    __syncthreads();

    // ---- zero-fill the latents row, then scatter ----
    {
        float4 z4 = make_float4(0.f, 0.f, 0.f, 0.f);
        float4* dst = (float4*)(latents + (size_t)row * L_DIM);
        #pragma unroll 4
        for (int i = 0; i < 16; i++) dst[t + (i << 8)] = z4;
    }
    __syncthreads();

    if (t < K_TOP) {
        int my = fin_idx[t]; float v = fin_val[t];
        int r = 0;
        for (int q = 0; q < K_TOP; q++) r += (int)(fin_idx[q] < my);
        g_tidx[row * K_TOP + r] = my;
        g_tval[row * K_TOP + r] = v;
        latents[(size_t)row * L_DIM + my] = v;
    }
}

// ============================ kernel 5: sparse decode ============================
__global__ void __launch_bounds__(256) decode_kernel(const float* __restrict__ Wd,
                                                     const float* __restrict__ pre_bias,
                                                     float* __restrict__ recons) {
    __shared__ int sidx[K_TOP];
    __shared__ float sval[K_TOP];
    int row = blockIdx.x, t = threadIdx.x;
    if (t < K_TOP) { sidx[t] = g_tidx[row * K_TOP + t]; sval[t] = g_tval[row * K_TOP + t]; }
    __syncthreads();
    float a0 = 0.f, a1 = 0.f, a2 = 0.f;
    #pragma unroll 4
    for (int j = 0; j < K_TOP; j++) {
        const float* w = Wd + (size_t)sidx[j] * D_DIM;
        float v = sval[j];
        a0 += v * __ldg(w + t);
        a1 += v * __ldg(w + t + 256);
        a2 += v * __ldg(w + t + 512);
    }
    float sd = g_std[row], mu = g_mu[row];
    float* Rr = recons + (size_t)row * D_DIM;
    Rr[t]       = (a0 + pre_bias[t])       * sd + mu;
    Rr[t + 256] = (a1 + pre_bias[t + 256]) * sd + mu;
    Rr[t + 512] = (a2 + pre_bias[t + 512]) * sd + mu;
}

// ============================ launch ============================
extern "C" void kernel_launch(void* const* d_in, const int* in_sizes, int n_in,
                              void* d_out, int out_size) {
    const float* x        = (const float*)d_in[0];
    const float* pre_bias = (const float*)d_in[1];
    const float* lat_bias = (const float*)d_in[2];
    const float* W_enc    = (const float*)d_in[3];
    const float* W_dec    = (const float*)d_in[4];

    float* outP = (float*)d_out;
    float* outL = outP + (size_t)B_DIM * L_DIM;
    float* outR = outL + (size_t)B_DIM * L_DIM;

    cudaFuncSetAttribute(gemm_kernel, cudaFuncAttributeMaxDynamicSharedMemorySize, GEMM_SMEM);

    prep_kernel<<<B_DIM + WP_BLOCKS, 256>>>(x, pre_bias, W_enc);
    gemm_kernel<<<dim3(L_DIM / 256, B_DIM / 128), 256, GEMM_SMEM>>>(lat_bias, outP);
    topk_kernel<<<B_DIM, 256>>>(outP, lat_bias, outL);
    decode_kernel<<<B_DIM, 256>>>(W_dec, pre_bias, outR);
}

// round 13
// speedup vs baseline: 1.5114x; 1.5114x over previous
#include <cuda_runtime.h>
#include <cstdint>

#define B_DIM 8192
#define D_DIM 768
#define L_DIM 16384
#define K_TOP 100
#define DELTA_BAND 2.5e-3f
#define UNC_CAP 192
#define CAND_CAP 512

// ============================ device scratch ============================
__device__ float g_Af[(size_t)B_DIM * D_DIM];   // A, MMA-fragment order
__device__ float g_Wf[(size_t)D_DIM * L_DIM];   // W_enc tf32, MMA-fragment order
__device__ float g_Xb[(size_t)B_DIM * D_DIM];   // exact fp32 (xn - pre_bias), row-major
__device__ float g_WT[(size_t)L_DIM * D_DIM];   // W_enc exact transpose, [L][D]
__device__ float g_mu[B_DIM];
__device__ float g_std[B_DIM];
__device__ int   g_tidx[B_DIM * K_TOP];
__device__ float g_tval[B_DIM * K_TOP];

// ============================ helpers ============================
__device__ __forceinline__ uint32_t smem_to_u32(const void* p) {
    uint32_t a;
    asm("{ .reg .u64 t; cvta.to.shared.u64 t, %1; cvt.u32.u64 %0, t; }" : "=r"(a) : "l"(p));
    return a;
}
__device__ __forceinline__ float tf32r(float x) {
    uint32_t u;
    asm("cvt.rna.tf32.f32 %0, %1;" : "=r"(u) : "f"(x));
    return __uint_as_float(u);
}
__device__ __forceinline__ float ldcs(const float* p) {
    float v;
    asm volatile("ld.global.cs.f32 %0, [%1];" : "=f"(v) : "l"(p));
    return v;
}
__device__ __forceinline__ void stcs4(float* p, float4 v) {
    asm volatile("st.global.cs.v4.f32 [%0], {%1, %2, %3, %4};"
                 :: "l"(p), "f"(v.x), "f"(v.y), "f"(v.z), "f"(v.w));
}
__device__ __forceinline__ void cp16(uint32_t saddr, const void* g) {
    asm volatile("cp.async.cg.shared.global [%0], [%1], 16;" :: "r"(saddr), "l"(g));
}
#define CP_COMMIT() asm volatile("cp.async.commit_group;" ::: "memory")
#define CP_WAIT0()  asm volatile("cp.async.wait_group 0;" ::: "memory")

__device__ __forceinline__ void mma_tf32(float* d, const uint32_t* a, const uint32_t* b) {
    asm volatile(
        "mma.sync.aligned.m16n8k8.row.col.f32.tf32.tf32.f32 "
        "{%0,%1,%2,%3}, {%4,%5,%6,%7}, {%8,%9}, {%0,%1,%2,%3};"
        : "+f"(d[0]), "+f"(d[1]), "+f"(d[2]), "+f"(d[3])
        : "r"(a[0]), "r"(a[1]), "r"(a[2]), "r"(a[3]), "r"(b[0]), "r"(b[1]));
}

__device__ __forceinline__ float key_to_float(uint32_t k) {
    uint32_t u = (k & 0x80000000u) ? (k & 0x7FFFFFFFu) : ~k;
    return __uint_as_float(u);
}
__device__ __forceinline__ uint32_t float_to_key(float f) {
    uint32_t u = __float_as_uint(f);
    return (u & 0x80000000u) ? ~u : (u | 0x80000000u);
}

// ============================ kernel 1: fused prep ============================
#define WP_KT (D_DIM / 32)        // 24
#define WP_NT (L_DIM / 256)       // 64
#define WP_BLOCKS (WP_KT * WP_NT) // 1536

__global__ void __launch_bounds__(256) prep_kernel(const float* __restrict__ x,
                                                   const float* __restrict__ pre_bias,
                                                   const float* __restrict__ W) {
    __shared__ float sw[32 * 257];
    __shared__ float rs[8], rs2[8], bc[2];
    int bid = blockIdx.x, t = threadIdx.x;

    if (bid < B_DIM) {
        int row = bid;
        const float* xr = x + (size_t)row * D_DIM;
        float v0 = xr[t], v1 = xr[t + 256], v2 = xr[t + 512];
        float s = v0 + v1 + v2;
        float s2 = v0 * v0 + v1 * v1 + v2 * v2;
        for (int o = 16; o; o >>= 1) {
            s  += __shfl_down_sync(0xFFFFFFFFu, s,  o);
            s2 += __shfl_down_sync(0xFFFFFFFFu, s2, o);
        }
        if ((t & 31) == 0) { rs[t >> 5] = s; rs2[t >> 5] = s2; }
        __syncthreads();
        if (t == 0) {
            float a = 0.f, b = 0.f;
            for (int w = 0; w < 8; w++) { a += rs[w]; b += rs2[w]; }
            float mu = a / (float)D_DIM;
            float var = b / (float)D_DIM - mu * mu;
            float sd = sqrtf(fmaxf(var, 0.0f));
            bc[0] = mu; bc[1] = sd;
            g_mu[row] = mu; g_std[row] = sd;
        }
        __syncthreads();
        float mu = bc[0], sd = bc[1];
        float inv = 1.0f / (sd + 1e-5f);
        int p = row >> 7, rloc = row & 127;
        int mb = rloc >> 4, r4 = rloc & 7, hi = (rloc >> 3) & 1;
        size_t pbase = ((size_t)p * 96) * 1024 + (size_t)mb * 128 + (size_t)r4 * 16 + hi;
        float* Xr = g_Xb + (size_t)row * D_DIM;
        #pragma unroll
        for (int j = 0; j < 3; j++) {
            int k = t + j * 256;
            float v = (j == 0 ? v0 : (j == 1 ? v1 : v2));
            float e = (v - mu) * inv - pre_bias[k];
            Xr[k] = e;
            int oct = k >> 3, kl = k & 7, cs = kl & 3, khi = kl >> 2;
            g_Af[pbase + (size_t)oct * 1024 + cs * 4 + 2 * khi] = tf32r(e);
        }
    } else {
        int wb = bid - B_DIM;
        int kt = wb % WP_KT, nt = wb / WP_KT;
        int k0 = kt * 32, n0 = nt * 256;

        #pragma unroll 8
        for (int r = 0; r < 32; r++)
            sw[r * 257 + t] = W[(size_t)(k0 + r) * L_DIM + n0 + t];
        __syncthreads();

        {
            int wrp = t >> 5, ln = t & 31;
            #pragma unroll 8
            for (int i = 0; i < 32; i++) {
                int lcol = wrp * 32 + i;
                g_WT[(size_t)(n0 + lcol) * D_DIM + k0 + ln] = sw[ln * 257 + lcol];
            }
        }

        #pragma unroll
        for (int ol = 0; ol < 4; ol++) {
            int oct = (k0 >> 3) + ol;
            float* out = g_Wf + ((size_t)oct * 2048 + (size_t)nt * 32) * 64;
            #pragma unroll
            for (int j = 0; j < 4; j++) {
                int pr = t * 4 + j;
                int nb8l = pr >> 5, r4 = (pr >> 2) & 7, cs = pr & 3;
                int n = nb8l * 8 + r4;
                out[pr * 2 + 0] = tf32r(sw[(ol * 8 + cs) * 257 + n]);
                out[pr * 2 + 1] = tf32r(sw[(ol * 8 + cs + 4) * 257 + n]);
            }
        }
    }
}

// ============================ kernel 3: encode GEMM (tf32 mma, KC=64, 2x96KB stages) ============================
#define KC 64
#define NCHUNK (D_DIM / KC)
#define STAGE_BYTES 98304
#define B_IN_STAGE 32768
#define GEMM_SMEM (2 * STAGE_BYTES)

__global__ void __launch_bounds__(256, 1) gemm_kernel(const float* __restrict__ lat_bias,
                                                      float* __restrict__ C) {
    extern __shared__ char smem[];
    uint32_t sb = smem_to_u32(smem);
    int t = threadIdx.x, wid = t >> 5, lane = t & 31;
    int wm = wid & 1, wn = wid >> 1;
    int r4 = lane >> 2, cs = lane & 3;
    int m0 = blockIdx.y * 128, n0 = blockIdx.x * 256;
    int panel = m0 >> 7, nb0 = n0 >> 3;

    auto issue = [&](int c, int slot) {
        uint32_t dst = sb + slot * STAGE_BYTES;
        const float* Asrc = g_Af + ((size_t)panel * 96 + c * 8) * 1024;
        #pragma unroll
        for (int i = 0; i < 8; i++) {
            int idx = t + i * 256;
            cp16(dst + idx * 16, Asrc + idx * 4);
        }
        #pragma unroll
        for (int j = 0; j < 8; j++) {
            const float* Bsrc = g_Wf + ((size_t)(c * 8 + j) * 2048 + nb0) * 64;
            #pragma unroll
            for (int i = 0; i < 2; i++) {
                int idx = t + i * 256;
                cp16(dst + B_IN_STAGE + j * 8192 + idx * 16, Bsrc + idx * 4);
            }
        }
    };

    auto loadFrags = [&](int slot, int k8, uint32_t a[4][4], uint32_t b[8][2]) {
        const float4* Aq = (const float4*)(smem + slot * STAGE_BYTES);
        const float2* Bp = (const float2*)(smem + slot * STAGE_BYTES + B_IN_STAGE);
        #pragma unroll
        for (int mt = 0; mt < 4; mt++) {
            float4 q = Aq[k8 * 256 + (wm * 4 + mt) * 32 + lane];
            a[mt][0] = __float_as_uint(q.x); a[mt][1] = __float_as_uint(q.y);
            a[mt][2] = __float_as_uint(q.z); a[mt][3] = __float_as_uint(q.w);
        }
        #pragma unroll
        for (int nt = 0; nt < 8; nt++) {
            float2 p2 = Bp[k8 * 1024 + (wn * 8 + nt) * 32 + lane];
            b[nt][0] = __float_as_uint(p2.x); b[nt][1] = __float_as_uint(p2.y);
        }
    };

    float acc[4][8][4];
    #pragma unroll
    for (int mt = 0; mt < 4; mt++)
        #pragma unroll
        for (int nt = 0; nt < 8; nt++)
            #pragma unroll
            for (int q = 0; q < 4; q++) acc[mt][nt][q] = 0.f;

    uint32_t aF[2][4][4], bF[2][8][2];

    issue(0, 0); CP_COMMIT();
    CP_WAIT0();
    __syncthreads();
    loadFrags(0, 0, aF[0], bF[0]);

    int pp = 0;
    for (int c = 0; c < NCHUNK; c++) {
        if (c + 1 < NCHUNK) { issue(c + 1, (c + 1) & 1); CP_COMMIT(); }
        int slot = c & 1;
        #pragma unroll
        for (int k8 = 0; k8 < 8; k8++) {
            int nxt = pp ^ 1;
            if (k8 < 7) {
                loadFrags(slot, k8 + 1, aF[nxt], bF[nxt]);
            } else if (c + 1 < NCHUNK) {
                CP_WAIT0();
                __syncthreads();
                loadFrags((c + 1) & 1, 0, aF[nxt], bF[nxt]);
            }
            #pragma unroll
            for (int mt = 0; mt < 4; mt++)
                #pragma unroll
                for (int nt = 0; nt < 8; nt++)
                    mma_tf32(acc[mt][nt], aF[pp][mt], bF[pp][nt]);
            pp ^= 1;
        }
    }

    #pragma unroll
    for (int mt = 0; mt < 4; mt++) {
        int m = m0 + wm * 64 + mt * 16 + r4;
        #pragma unroll
        for (int nt = 0; nt < 8; nt++) {
            int n = n0 + wn * 64 + nt * 8 + cs * 2;
            float2 bb = *(const float2*)(lat_bias + n);
            float2 v0 = make_float2(acc[mt][nt][0] + bb.x, acc[mt][nt][1] + bb.y);
            float2 v1 = make_float2(acc[mt][nt][2] + bb.x, acc[mt][nt][3] + bb.y);
            *(float2*)(C + (size_t)m * L_DIM + n) = v0;
            *(float2*)(C + (size_t)(m + 8) * L_DIM + n) = v1;
        }
    }
}

// ============================ kernel 4: statistics-guided top-k + row write ============================
__global__ void __launch_bounds__(256) topk_kernel(const float* __restrict__ P,
                                                   const float* __restrict__ lat_bias,
                                                   float* __restrict__ latents) {
    __shared__ unsigned short keys16[16384];
    __shared__ float s_redf[8];
    __shared__ int   s_redi[8];
    __shared__ int   s_total;
    __shared__ float s_rms;
    __shared__ int   s_cnt;
    __shared__ int      cand_idx[CAND_CAP];
    __shared__ uint32_t srt_key[CAND_CAP];
    __shared__ int      srt_idx[CAND_CAP];
    __shared__ int      unc_ix[UNC_CAP];
    __shared__ float    unc_ex[UNC_CAP];
    __shared__ int      fin_idx[K_TOP];
    __shared__ float    fin_val[K_TOP];

    int row = blockIdx.x, t = threadIdx.x, lane = t & 31, wid = t >> 5;
    const float* Pr = P + (size_t)row * L_DIM;

    float sum2 = 0.f;
    #pragma unroll 4
    for (int i = 0; i < 64; i++) {
        float v = ldcs(Pr + t + (i << 8));      // evict-first: one-shot stream
        keys16[t + (i << 8)] = (unsigned short)(float_to_key(v) >> 16);
        sum2 += v * v;
    }
    for (int o = 16; o; o >>= 1) sum2 += __shfl_down_sync(0xFFFFFFFFu, sum2, o);
    if (lane == 0) s_redf[wid] = sum2;
    __syncthreads();
    if (t == 0) {
        float a = 0.f;
        for (int w = 0; w < 8; w++) a += s_redf[w];
        s_rms = sqrtf(a / (float)L_DIM);
    }
    __syncthreads();
    float rms = s_rms;

    int T = (int)(float_to_key(2.33f * rms) >> 16);
    int c = 0;
    for (int iter = 0; iter < 64; iter++) {
        int local = 0;
        #pragma unroll 4
        for (int i = 0; i < 64; i++)
            local += (int)((int)keys16[t + (i << 8)] >= T);
        for (int o = 16; o; o >>= 1) local += __shfl_down_sync(0xFFFFFFFFu, local, o);
        if (lane == 0) s_redi[wid] = local;
        __syncthreads();
        if (t == 0) {
            int tot = 0;
            for (int w = 0; w < 8; w++) tot += s_redi[w];
            s_total = tot;
        }
        __syncthreads();
        c = s_total;
        __syncthreads();
        if (c < K_TOP)            T = (T >= 32) ? T - 32 : 0;
        else if (c > CAND_CAP)    T += 32;
        else break;
        if (T == 0 && c >= K_TOP) break;
    }

    uint32_t klo = 0, khi = 0;
    for (int pass = 0; pass < 3; pass++) {
        if (t == 0) s_cnt = 0;
        __syncthreads();
        #pragma unroll 4
        for (int i = 0; i < 64; i++) {
            int idx = t + (i << 8);
            bool p = ((int)keys16[idx] >= T);
            unsigned m = __ballot_sync(0xFFFFFFFFu, p);
            if (m) {
                int ldr = __ffs(m) - 1;
                int base = 0;
                if (lane == ldr) base = atomicAdd(&s_cnt, __popc(m));
                base = __shfl_sync(0xFFFFFFFFu, base, ldr);
                if (p) {
                    int slot = base + __popc(m & ((1u << lane) - 1u));
                    if (slot < CAND_CAP) cand_idx[slot] = idx;
                }
            }
        }
        __syncthreads();
        c = s_cnt < CAND_CAP ? s_cnt : CAND_CAP;

        for (int j = t; j < CAND_CAP; j += 256) {
            if (j < c) {
                int idx = cand_idx[j];
                srt_key[j] = float_to_key(Pr[idx]);
                srt_idx[j] = idx;
            } else {
                srt_key[j] = 0u;
                srt_idx[j] = 0x7FFFFFFF;
            }
        }
        __syncthreads();

        for (int k2 = 2; k2 <= CAND_CAP; k2 <<= 1) {
            for (int j2 = k2 >> 1; j2 > 0; j2 >>= 1) {
                for (int i = t; i < CAND_CAP; i += 256) {
                    int ixj = i ^ j2;
                    if (ixj > i) {
                        uint32_t ki = srt_key[i], kj = srt_key[ixj];
                        int ii = srt_idx[i], ij = srt_idx[ixj];
                        bool gt = (ki > kj) || (ki == kj && ii < ij);
                        bool dir = ((i & k2) == 0);
                        if (dir ? !gt : gt) {
                            srt_key[i] = kj; srt_key[ixj] = ki;
                            srt_idx[i] = ij; srt_idx[ixj] = ii;
                        }
                    }
                }
                __syncthreads();
            }
        }

        float v100 = key_to_float(srt_key[K_TOP - 1]);
        klo = float_to_key(v100 - DELTA_BAND);
        khi = float_to_key(v100 + DELTA_BAND);
        if ((int)(klo >> 16) >= T || T == 0) break;
        T = (int)(klo >> 16);
        __syncthreads();
    }

    {
        int l0 = 0, l1 = 0;
        for (int j = t; j < CAND_CAP; j += 256) {
            l0 += (int)(srt_key[j] > khi);
            l1 += (int)(srt_key[j] >= klo);
        }
        int v = l0;
        for (int o = 16; o; o >>= 1) v += __shfl_down_sync(0xFFFFFFFFu, v, o);
        if (lane == 0) s_redi[wid] = v;
        __syncthreads();
        if (t == 0) { int tot = 0; for (int w = 0; w < 8; w++) tot += s_redi[w]; s_total = tot; }
        __syncthreads();
        l0 = s_total;
        __syncthreads();
        v = l1;
        for (int o = 16; o; o >>= 1) v += __shfl_down_sync(0xFFFFFFFFu, v, o);
        if (lane == 0) s_redi[wid] = v;
        __syncthreads();
        if (t == 0) { int tot = 0; for (int w = 0; w < 8; w++) tot += s_redi[w]; s_total = tot; }
        __syncthreads();
        l1 = s_total;
        __syncthreads();
        if (t == 0) { s_redi[0] = l0; s_redi[1] = l1; }
        __syncthreads();
    }
    int j0 = s_redi[0];
    int j1 = s_redi[1];
    if (j0 > K_TOP - 1) j0 = K_TOP - 1;
    int U = j1 - j0; if (U > UNC_CAP) U = UNC_CAP;
    int need = K_TOP - j0;

    if (t < U) unc_ix[t] = srt_idx[j0 + t];
    __syncthreads();
    const float* Xr = g_Xb + (size_t)row * D_DIM;
    for (int q = wid; q < U; q += 8) {
        const float* w = g_WT + (size_t)unc_ix[q] * D_DIM;
        float s = 0.f, comp = 0.f;
        for (int d = lane; d < D_DIM; d += 32) {
            float prod = Xr[d] * w[d];
            float tn = s + prod;
            if (fabsf(s) >= fabsf(prod)) comp += (s - tn) + prod;
            else                         comp += (prod - tn) + s;
            s = tn;
        }
        s += comp;
        for (int o = 16; o; o >>= 1) s += __shfl_xor_sync(0xFFFFFFFFu, s, o);
        if (lane == 0) unc_ex[q] = s + lat_bias[unc_ix[q]];
    }
    __syncthreads();

    if (t < j0) { fin_idx[t] = srt_idx[t]; fin_val[t] = key_to_float(srt_key[t]); }
    __syncthreads();
    if (t == 0) {
        for (int a = 1; a < U; a++) {
            float vv = unc_ex[a]; int ii = unc_ix[a]; int b = a - 1;
            while (b >= 0 && (unc_ex[b] < vv || (unc_ex[b] == vv && unc_ix[b] > ii))) {
                unc_ex[b + 1] = unc_ex[b]; unc_ix[b + 1] = unc_ix[b]; b--;
            }
            unc_ex[b + 1] = vv; unc_ix[b + 1] = ii;
        }
        for (int q = 0; q < need; q++) {
            fin_idx[j0 + q] = unc_ix[q]; fin_val[j0 + q] = unc_ex[q];
        }
    }
    __syncthreads();

    // ---- stream zeros over the whole latents row (evict-first stores) ----
    {
        float4 z4 = make_float4(0.f, 0.f, 0.f, 0.f);
        float* dst = latents + (size_t)row * L_DIM;
        #pragma unroll 4
        for (int i = 0; i < 16; i++) stcs4(dst + (t + (i << 8)) * 4, z4);
    }
    __syncthreads();   // orders zero-stores before the scatter below (block scope)

    if (t < K_TOP) {
        int my = fin_idx[t]; float v = fin_val[t];
        int r = 0;
        for (int q = 0; q < K_TOP; q++) r += (int)(fin_idx[q] < my);
        g_tidx[row * K_TOP + r] = my;
        g_tval[row * K_TOP + r] = v;
        latents[(size_t)row * L_DIM + my] = v;
    }
}

// ============================ kernel 5: sparse decode ============================
__global__ void __launch_bounds__(256) decode_kernel(const float* __restrict__ Wd,
                                                     const float* __restrict__ pre_bias,
                                                     float* __restrict__ recons) {
    __shared__ int sidx[K_TOP];
    __shared__ float sval[K_TOP];
    int row = blockIdx.x, t = threadIdx.x;
    if (t < K_TOP) { sidx[t] = g_tidx[row * K_TOP + t]; sval[t] = g_tval[row * K_TOP + t]; }
    __syncthreads();
    float a0 = 0.f, a1 = 0.f, a2 = 0.f;
    #pragma unroll 4
    for (int j = 0; j < K_TOP; j++) {
        const float* w = Wd + (size_t)sidx[j] * D_DIM;
        float v = sval[j];
        a0 += v * __ldg(w + t);
        a1 += v * __ldg(w + t + 256);
        a2 += v * __ldg(w + t + 512);
    }
    float sd = g_std[row], mu = g_mu[row];
    float* Rr = recons + (size_t)row * D_DIM;
    Rr[t]       = (a0 + pre_bias[t])       * sd + mu;
    Rr[t + 256] = (a1 + pre_bias[t + 256]) * sd + mu;
    Rr[t + 512] = (a2 + pre_bias[t + 512]) * sd + mu;
}

// ============================ launch ============================
extern "C" void kernel_launch(void* const* d_in, const int* in_sizes, int n_in,
                              void* d_out, int out_size) {
    const float* x        = (const float*)d_in[0];
    const float* pre_bias = (const float*)d_in[1];
    const float* lat_bias = (const float*)d_in[2];
    const float* W_enc    = (const float*)d_in[3];
    const float* W_dec    = (const float*)d_in[4];

    float* outP = (float*)d_out;
    float* outL = outP + (size_t)B_DIM * L_DIM;
    float* outR = outL + (size_t)B_DIM * L_DIM;

    cudaFuncSetAttribute(gemm_kernel, cudaFuncAttributeMaxDynamicSharedMemorySize, GEMM_SMEM);

    prep_kernel<<<B_DIM + WP_BLOCKS, 256>>>(x, pre_bias, W_enc);
    gemm_kernel<<<dim3(L_DIM / 256, B_DIM / 128), 256, GEMM_SMEM>>>(lat_bias, outP);
    topk_kernel<<<B_DIM, 256>>>(outP, lat_bias, outL);
    decode_kernel<<<B_DIM, 256>>>(W_dec, pre_bias, outR);
}

// round 14
// speedup vs baseline: 1.5285x; 1.0113x over previous
#include <cuda_runtime.h>
#include <cstdint>

#define B_DIM 8192
#define D_DIM 768
#define L_DIM 16384
#define K_TOP 100
#define DELTA_BAND 2.5e-3f
#define UNC_CAP 192
#define CAND_CAP 512

// ============================ device scratch ============================
__device__ float g_Af[(size_t)B_DIM * D_DIM];   // A, MMA-fragment order
__device__ float g_Wf[(size_t)D_DIM * L_DIM];   // W_enc tf32, MMA-fragment order
__device__ float g_Xb[(size_t)B_DIM * D_DIM];   // exact fp32 (xn - pre_bias), row-major
__device__ float g_WT[(size_t)L_DIM * D_DIM];   // W_enc exact transpose, [L][D]
__device__ float g_mu[B_DIM];
__device__ float g_std[B_DIM];
__device__ int   g_tidx[B_DIM * K_TOP];
__device__ float g_tval[B_DIM * K_TOP];

// ============================ helpers ============================
__device__ __forceinline__ uint32_t smem_to_u32(const void* p) {
    uint32_t a;
    asm("{ .reg .u64 t; cvta.to.shared.u64 t, %1; cvt.u32.u64 %0, t; }" : "=r"(a) : "l"(p));
    return a;
}
__device__ __forceinline__ float tf32r(float x) {
    uint32_t u;
    asm("cvt.rna.tf32.f32 %0, %1;" : "=r"(u) : "f"(x));
    return __uint_as_float(u);
}
__device__ __forceinline__ void cp16(uint32_t saddr, const void* g) {
    asm volatile("cp.async.cg.shared.global [%0], [%1], 16;" :: "r"(saddr), "l"(g));
}
#define CP_COMMIT() asm volatile("cp.async.commit_group;" ::: "memory")
#define CP_WAIT0()  asm volatile("cp.async.wait_group 0;" ::: "memory")

__device__ __forceinline__ void mma_tf32(float* d, const uint32_t* a, const uint32_t* b) {
    asm volatile(
        "mma.sync.aligned.m16n8k8.row.col.f32.tf32.tf32.f32 "
        "{%0,%1,%2,%3}, {%4,%5,%6,%7}, {%8,%9}, {%0,%1,%2,%3};"
        : "+f"(d[0]), "+f"(d[1]), "+f"(d[2]), "+f"(d[3])
        : "r"(a[0]), "r"(a[1]), "r"(a[2]), "r"(a[3]), "r"(b[0]), "r"(b[1]));
}

__device__ __forceinline__ float key_to_float(uint32_t k) {
    uint32_t u = (k & 0x80000000u) ? (k & 0x7FFFFFFFu) : ~k;
    return __uint_as_float(u);
}
__device__ __forceinline__ uint32_t float_to_key(float f) {
    uint32_t u = __float_as_uint(f);
    return (u & 0x80000000u) ? ~u : (u | 0x80000000u);
}

// ============================ kernel 1: fused prep ============================
#define WP_KT (D_DIM / 32)        // 24
#define WP_NT (L_DIM / 256)       // 64
#define WP_BLOCKS (WP_KT * WP_NT) // 1536

__global__ void __launch_bounds__(256) prep_kernel(const float* __restrict__ x,
                                                   const float* __restrict__ pre_bias,
                                                   const float* __restrict__ W) {
    __shared__ float sw[32 * 257];
    __shared__ float rs[8], rs2[8], bc[2];
    int bid = blockIdx.x, t = threadIdx.x;

    if (bid < B_DIM) {
        int row = bid;
        const float* xr = x + (size_t)row * D_DIM;
        float v0 = xr[t], v1 = xr[t + 256], v2 = xr[t + 512];
        float s = v0 + v1 + v2;
        float s2 = v0 * v0 + v1 * v1 + v2 * v2;
        for (int o = 16; o; o >>= 1) {
            s  += __shfl_down_sync(0xFFFFFFFFu, s,  o);
            s2 += __shfl_down_sync(0xFFFFFFFFu, s2, o);
        }
        if ((t & 31) == 0) { rs[t >> 5] = s; rs2[t >> 5] = s2; }
        __syncthreads();
        if (t == 0) {
            float a = 0.f, b = 0.f;
            for (int w = 0; w < 8; w++) { a += rs[w]; b += rs2[w]; }
            float mu = a / (float)D_DIM;
            float var = b / (float)D_DIM - mu * mu;
            float sd = sqrtf(fmaxf(var, 0.0f));
            bc[0] = mu; bc[1] = sd;
            g_mu[row] = mu; g_std[row] = sd;
        }
        __syncthreads();
        float mu = bc[0], sd = bc[1];
        float inv = 1.0f / (sd + 1e-5f);
        int p = row >> 7, rloc = row & 127;
        int mb = rloc >> 4, r4 = rloc & 7, hi = (rloc >> 3) & 1;
        size_t pbase = ((size_t)p * 96) * 1024 + (size_t)mb * 128 + (size_t)r4 * 16 + hi;
        float* Xr = g_Xb + (size_t)row * D_DIM;
        #pragma unroll
        for (int j = 0; j < 3; j++) {
            int k = t + j * 256;
            float v = (j == 0 ? v0 : (j == 1 ? v1 : v2));
            float e = (v - mu) * inv - pre_bias[k];
            Xr[k] = e;
            int oct = k >> 3, kl = k & 7, cs = kl & 3, khi = kl >> 2;
            g_Af[pbase + (size_t)oct * 1024 + cs * 4 + 2 * khi] = tf32r(e);
        }
    } else {
        int wb = bid - B_DIM;
        int kt = wb % WP_KT, nt = wb / WP_KT;
        int k0 = kt * 32, n0 = nt * 256;

        #pragma unroll 8
        for (int r = 0; r < 32; r++)
            sw[r * 257 + t] = W[(size_t)(k0 + r) * L_DIM + n0 + t];
        __syncthreads();

        {
            int wrp = t >> 5, ln = t & 31;
            #pragma unroll 8
            for (int i = 0; i < 32; i++) {
                int lcol = wrp * 32 + i;
                g_WT[(size_t)(n0 + lcol) * D_DIM + k0 + ln] = sw[ln * 257 + lcol];
            }
        }

        #pragma unroll
        for (int ol = 0; ol < 4; ol++) {
            int oct = (k0 >> 3) + ol;
            float* out = g_Wf + ((size_t)oct * 2048 + (size_t)nt * 32) * 64;
            #pragma unroll
            for (int j = 0; j < 4; j++) {
                int pr = t * 4 + j;
                int nb8l = pr >> 5, r4 = (pr >> 2) & 7, cs = pr & 3;
                int n = nb8l * 8 + r4;
                out[pr * 2 + 0] = tf32r(sw[(ol * 8 + cs) * 257 + n]);
                out[pr * 2 + 1] = tf32r(sw[(ol * 8 + cs + 4) * 257 + n]);
            }
        }
    }
}

// ============================ kernel 3: persistent encode GEMM ============================
// 148 persistent CTAs, each owns a contiguous run of 128x256 tiles (panel-major
// order -> one A panel per CTA, L2-hot). Chunk pipeline flattened across tiles:
// the cp.async stream never drains at tile boundaries.
#define KC 64
#define NCHUNK (D_DIM / KC)              // 12
#define STAGE_BYTES 98304
#define B_IN_STAGE 32768
#define GEMM_SMEM (2 * STAGE_BYTES)
#define GEMM_CTAS 148
#define TOT_TILES ((B_DIM / 128) * (L_DIM / 256))   // 4096

__global__ void __launch_bounds__(256, 1) gemm_kernel(const float* __restrict__ lat_bias,
                                                      float* __restrict__ C) {
    extern __shared__ char smem[];
    uint32_t sb = smem_to_u32(smem);
    int t = threadIdx.x, wid = t >> 5, lane = t & 31;
    int wm = wid & 1, wn = wid >> 1;
    int r4 = lane >> 2, cs = lane & 3;

    // contiguous tile range: first `rem` CTAs get base+1 tiles
    const int base = TOT_TILES / GEMM_CTAS;          // 27
    const int rem  = TOT_TILES % GEMM_CTAS;          // 100
    int cta = blockIdx.x;
    int start = (cta < rem) ? cta * (base + 1) : rem * (base + 1) + (cta - rem) * base;
    int ntile = (cta < rem) ? base + 1 : base;
    int gtotal = ntile * NCHUNK;

    // issue chunk g (g = it*NCHUNK + c) into slot g&1
    auto issue_g = [&](int g) {
        int tl = start + g / NCHUNK;
        int c  = g % NCHUNK;
        int panel = tl >> 6;
        int nb0 = (tl & 63) * 32;
        uint32_t dst = sb + (g & 1) * STAGE_BYTES;
        const float* Asrc = g_Af + ((size_t)panel * 96 + c * 8) * 1024;
        #pragma unroll
        for (int i = 0; i < 8; i++) {
            int idx = t + i * 256;
            cp16(dst + idx * 16, Asrc + idx * 4);
        }
        #pragma unroll
        for (int j = 0; j < 8; j++) {
            const float* Bsrc = g_Wf + ((size_t)(c * 8 + j) * 2048 + nb0) * 64;
            #pragma unroll
            for (int i = 0; i < 2; i++) {
                int idx = t + i * 256;
                cp16(dst + B_IN_STAGE + j * 8192 + idx * 16, Bsrc + idx * 4);
            }
        }
    };

    auto loadFrags = [&](int slot, int k8, uint32_t a[4][4], uint32_t b[8][2]) {
        const float4* Aq = (const float4*)(smem + slot * STAGE_BYTES);
        const float2* Bp = (const float2*)(smem + slot * STAGE_BYTES + B_IN_STAGE);
        #pragma unroll
        for (int mt = 0; mt < 4; mt++) {
            float4 q = Aq[k8 * 256 + (wm * 4 + mt) * 32 + lane];
            a[mt][0] = __float_as_uint(q.x); a[mt][1] = __float_as_uint(q.y);
            a[mt][2] = __float_as_uint(q.z); a[mt][3] = __float_as_uint(q.w);
        }
        #pragma unroll
        for (int nt = 0; nt < 8; nt++) {
            float2 p2 = Bp[k8 * 1024 + (wn * 8 + nt) * 32 + lane];
            b[nt][0] = __float_as_uint(p2.x); b[nt][1] = __float_as_uint(p2.y);
        }
    };

    uint32_t aF[2][4][4], bF[2][8][2];

    issue_g(0); CP_COMMIT();
    CP_WAIT0();
    __syncthreads();
    loadFrags(0, 0, aF[0], bF[0]);

    int pp = 0;
    for (int it = 0; it < ntile; it++) {
        float acc[4][8][4];
        #pragma unroll
        for (int mt = 0; mt < 4; mt++)
            #pragma unroll
            for (int nt = 0; nt < 8; nt++)
                #pragma unroll
                for (int q = 0; q < 4; q++) acc[mt][nt][q] = 0.f;

        for (int c = 0; c < NCHUNK; c++) {
            int gc = it * NCHUNK + c;
            if (gc + 1 < gtotal) { issue_g(gc + 1); CP_COMMIT(); }
            int slot = gc & 1;
            #pragma unroll
            for (int k8 = 0; k8 < 8; k8++) {
                int nxt = pp ^ 1;
                if (k8 < 7) {
                    loadFrags(slot, k8 + 1, aF[nxt], bF[nxt]);
                } else if (gc + 1 < gtotal) {
                    CP_WAIT0();
                    __syncthreads();
                    loadFrags((gc + 1) & 1, 0, aF[nxt], bF[nxt]);
                }
                #pragma unroll
                for (int mt = 0; mt < 4; mt++)
                    #pragma unroll
                    for (int nt = 0; nt < 8; nt++)
                        mma_tf32(acc[mt][nt], aF[pp][mt], bF[pp][nt]);
                pp ^= 1;
            }
        }

        // epilogue for tile `it` (overlaps the cp.async of the next tile's chunk 0/1)
        int tl = start + it;
        int m0 = (tl >> 6) * 128, n0 = (tl & 63) * 256;
        #pragma unroll
        for (int mt = 0; mt < 4; mt++) {
            int m = m0 + wm * 64 + mt * 16 + r4;
            #pragma unroll
            for (int nt = 0; nt < 8; nt++) {
                int n = n0 + wn * 64 + nt * 8 + cs * 2;
                float2 bb = *(const float2*)(lat_bias + n);
                float2 v0 = make_float2(acc[mt][nt][0] + bb.x, acc[mt][nt][1] + bb.y);
                float2 v1 = make_float2(acc[mt][nt][2] + bb.x, acc[mt][nt][3] + bb.y);
                *(float2*)(C + (size_t)m * L_DIM + n) = v0;
                *(float2*)(C + (size_t)(m + 8) * L_DIM + n) = v1;
            }
        }
    }
}

// ============================ kernel 4: statistics-guided top-k + row write ============================
__global__ void __launch_bounds__(256) topk_kernel(const float* __restrict__ P,
                                                   const float* __restrict__ lat_bias,
                                                   float* __restrict__ latents) {
    __shared__ unsigned short keys16[16384];
    __shared__ float s_redf[8];
    __shared__ int   s_redi[8];
    __shared__ int   s_total;
    __shared__ float s_rms;
    __shared__ int   s_cnt;
    __shared__ int      cand_idx[CAND_CAP];
    __shared__ uint32_t srt_key[CAND_CAP];
    __shared__ int      srt_idx[CAND_CAP];
    __shared__ int      unc_ix[UNC_CAP];
    __shared__ float    unc_ex[UNC_CAP];
    __shared__ int      fin_idx[K_TOP];
    __shared__ float    fin_val[K_TOP];

    int row = blockIdx.x, t = threadIdx.x, lane = t & 31, wid = t >> 5;
    const float* Pr = P + (size_t)row * L_DIM;

    float sum2 = 0.f;
    #pragma unroll 4
    for (int i = 0; i < 64; i++) {
        float v = Pr[t + (i << 8)];
        keys16[t + (i << 8)] = (unsigned short)(float_to_key(v) >> 16);
        sum2 += v * v;
    }
    for (int o = 16; o; o >>= 1) sum2 += __shfl_down_sync(0xFFFFFFFFu, sum2, o);
    if (lane == 0) s_redf[wid] = sum2;
    __syncthreads();
    if (t == 0) {
        float a = 0.f;
        for (int w = 0; w < 8; w++) a += s_redf[w];
        s_rms = sqrtf(a / (float)L_DIM);
    }
    __syncthreads();
    float rms = s_rms;

    int T = (int)(float_to_key(2.33f * rms) >> 16);
    int c = 0;
    for (int iter = 0; iter < 64; iter++) {
        int local = 0;
        #pragma unroll 4
        for (int i = 0; i < 64; i++)
            local += (int)((int)keys16[t + (i << 8)] >= T);
        for (int o = 16; o; o >>= 1) local += __shfl_down_sync(0xFFFFFFFFu, local, o);
        if (lane == 0) s_redi[wid] = local;
        __syncthreads();
        if (t == 0) {
            int tot = 0;
            for (int w = 0; w < 8; w++) tot += s_redi[w];
            s_total = tot;
        }
        __syncthreads();
        c = s_total;
        __syncthreads();
        if (c < K_TOP)            T = (T >= 32) ? T - 32 : 0;
        else if (c > CAND_CAP)    T += 32;
        else break;
        if (T == 0 && c >= K_TOP) break;
    }

    uint32_t klo = 0, khi = 0;
    for (int pass = 0; pass < 3; pass++) {
        if (t == 0) s_cnt = 0;
        __syncthreads();
        #pragma unroll 4
        for (int i = 0; i < 64; i++) {
            int idx = t + (i << 8);
            bool p = ((int)keys16[idx] >= T);
            unsigned m = __ballot_sync(0xFFFFFFFFu, p);
            if (m) {
                int ldr = __ffs(m) - 1;
                int base = 0;
                if (lane == ldr) base = atomicAdd(&s_cnt, __popc(m));
                base = __shfl_sync(0xFFFFFFFFu, base, ldr);
                if (p) {
                    int slot = base + __popc(m & ((1u << lane) - 1u));
                    if (slot < CAND_CAP) cand_idx[slot] = idx;
                }
            }
        }
        __syncthreads();
        c = s_cnt < CAND_CAP ? s_cnt : CAND_CAP;

        for (int j = t; j < CAND_CAP; j += 256) {
            if (j < c) {
                int idx = cand_idx[j];
                srt_key[j] = float_to_key(Pr[idx]);
                srt_idx[j] = idx;
            } else {
                srt_key[j] = 0u;
                srt_idx[j] = 0x7FFFFFFF;
            }
        }
        __syncthreads();

        for (int k2 = 2; k2 <= CAND_CAP; k2 <<= 1) {
            for (int j2 = k2 >> 1; j2 > 0; j2 >>= 1) {
                for (int i = t; i < CAND_CAP; i += 256) {
                    int ixj = i ^ j2;
                    if (ixj > i) {
                        uint32_t ki = srt_key[i], kj = srt_key[ixj];
                        int ii = srt_idx[i], ij = srt_idx[ixj];
                        bool gt = (ki > kj) || (ki == kj && ii < ij);
                        bool dir = ((i & k2) == 0);
                        if (dir ? !gt : gt) {
                            srt_key[i] = kj; srt_key[ixj] = ki;
                            srt_idx[i] = ij; srt_idx[ixj] = ii;
                        }
                    }
                }
                __syncthreads();
            }
        }

        float v100 = key_to_float(srt_key[K_TOP - 1]);
        klo = float_to_key(v100 - DELTA_BAND);
        khi = float_to_key(v100 + DELTA_BAND);
        if ((int)(klo >> 16) >= T || T == 0) break;
        T = (int)(klo >> 16);
        __syncthreads();
    }

    {
        int l0 = 0, l1 = 0;
        for (int j = t; j < CAND_CAP; j += 256) {
            l0 += (int)(srt_key[j] > khi);
            l1 += (int)(srt_key[j] >= klo);
        }
        int v = l0;
        for (int o = 16; o; o >>= 1) v += __shfl_down_sync(0xFFFFFFFFu, v, o);
        if (lane == 0) s_redi[wid] = v;
        __syncthreads();
        if (t == 0) { int tot = 0; for (int w = 0; w < 8; w++) tot += s_redi[w]; s_total = tot; }
        __syncthreads();
        l0 = s_total;
        __syncthreads();
        v = l1;
        for (int o = 16; o; o >>= 1) v += __shfl_down_sync(0xFFFFFFFFu, v, o);
        if (lane == 0) s_redi[wid] = v;
        __syncthreads();
        if (t == 0) { int tot = 0; for (int w = 0; w < 8; w++) tot += s_redi[w]; s_total = tot; }
        __syncthreads();
        l1 = s_total;
        __syncthreads();
        if (t == 0) { s_redi[0] = l0; s_redi[1] = l1; }
        __syncthreads();
    }
    int j0 = s_redi[0];
    int j1 = s_redi[1];
    if (j0 > K_TOP - 1) j0 = K_TOP - 1;
    int U = j1 - j0; if (U > UNC_CAP) U = UNC_CAP;
    int need = K_TOP - j0;

    if (t < U) unc_ix[t] = srt_idx[j0 + t];
    __syncthreads();
    const float* Xr = g_Xb + (size_t)row * D_DIM;
    for (int q = wid; q < U; q += 8) {
        const float* w = g_WT + (size_t)unc_ix[q] * D_DIM;
        float s = 0.f, comp = 0.f;
        for (int d = lane; d < D_DIM; d += 32) {
            float prod = Xr[d] * w[d];
            float tn = s + prod;
            if (fabsf(s) >= fabsf(prod)) comp += (s - tn) + prod;
            else                         comp += (prod - tn) + s;
            s = tn;
        }
        s += comp;
        for (int o = 16; o; o >>= 1) s += __shfl_xor_sync(0xFFFFFFFFu, s, o);
        if (lane == 0) unc_ex[q] = s + lat_bias[unc_ix[q]];
    }
    __syncthreads();

    if (t < j0) { fin_idx[t] = srt_idx[t]; fin_val[t] = key_to_float(srt_key[t]); }
    __syncthreads();
    if (t == 0) {
        for (int a = 1; a < U; a++) {
            float vv = unc_ex[a]; int ii = unc_ix[a]; int b = a - 1;
            while (b >= 0 && (unc_ex[b] < vv || (unc_ex[b] == vv && unc_ix[b] > ii))) {
                unc_ex[b + 1] = unc_ex[b]; unc_ix[b + 1] = unc_ix[b]; b--;
            }
            unc_ex[b + 1] = vv; unc_ix[b + 1] = ii;
        }
        for (int q = 0; q < need; q++) {
            fin_idx[j0 + q] = unc_ix[q]; fin_val[j0 + q] = unc_ex[q];
        }
    }
    __syncthreads();

    // ---- stream zeros over the whole latents row ----
    {
        float4 z4 = make_float4(0.f, 0.f, 0.f, 0.f);
        float4* dst = (float4*)(latents + (size_t)row * L_DIM);
        #pragma unroll 4
        for (int i = 0; i < 16; i++) dst[t + (i << 8)] = z4;
    }
    __syncthreads();

    if (t < K_TOP) {
        int my = fin_idx[t]; float v = fin_val[t];
        int r = 0;
        for (int q = 0; q < K_TOP; q++) r += (int)(fin_idx[q] < my);
        g_tidx[row * K_TOP + r] = my;
        g_tval[row * K_TOP + r] = v;
        latents[(size_t)row * L_DIM + my] = v;
    }
}

// ============================ kernel 5: sparse decode ============================
__global__ void __launch_bounds__(256) decode_kernel(const float* __restrict__ Wd,
                                                     const float* __restrict__ pre_bias,
                                                     float* __restrict__ recons) {
    __shared__ int sidx[K_TOP];
    __shared__ float sval[K_TOP];
    int row = blockIdx.x, t = threadIdx.x;
    if (t < K_TOP) { sidx[t] = g_tidx[row * K_TOP + t]; sval[t] = g_tval[row * K_TOP + t]; }
    __syncthreads();
    float a0 = 0.f, a1 = 0.f, a2 = 0.f;
    #pragma unroll 4
    for (int j = 0; j < K_TOP; j++) {
        const float* w = Wd + (size_t)sidx[j] * D_DIM;
        float v = sval[j];
        a0 += v * __ldg(w + t);
        a1 += v * __ldg(w + t + 256);
        a2 += v * __ldg(w + t + 512);
    }
    float sd = g_std[row], mu = g_mu[row];
    float* Rr = recons + (size_t)row * D_DIM;
    Rr[t]       = (a0 + pre_bias[t])       * sd + mu;
    Rr[t + 256] = (a1 + pre_bias[t + 256]) * sd + mu;
    Rr[t + 512] = (a2 + pre_bias[t + 512]) * sd + mu;
}

// ============================ launch ============================
extern "C" void kernel_launch(void* const* d_in, const int* in_sizes, int n_in,
                              void* d_out, int out_size) {
    const float* x        = (const float*)d_in[0];
    const float* pre_bias = (const float*)d_in[1];
    const float* lat_bias = (const float*)d_in[2];
    const float* W_enc    = (const float*)d_in[3];
    const float* W_dec    = (const float*)d_in[4];

    float* outP = (float*)d_out;
    float* outL = outP + (size_t)B_DIM * L_DIM;
    float* outR = outL + (size_t)B_DIM * L_DIM;

    cudaFuncSetAttribute(gemm_kernel, cudaFuncAttributeMaxDynamicSharedMemorySize, GEMM_SMEM);

    prep_kernel<<<B_DIM + WP_BLOCKS, 256>>>(x, pre_bias, W_enc);
    gemm_kernel<<<GEMM_CTAS, 256, GEMM_SMEM>>>(lat_bias, outP);
    topk_kernel<<<B_DIM, 256>>>(outP, lat_bias, outL);
    decode_kernel<<<B_DIM, 256>>>(W_dec, pre_bias, outR);
}

// round 15
// speedup vs baseline: 1.5836x; 1.0361x over previous
#include <cuda_runtime.h>
#include <cstdint>

#define B_DIM 8192
#define D_DIM 768
#define L_DIM 16384
#define K_TOP 100
#define DELTA_BAND 2.5e-3f
#define UNC_CAP 192
#define CAND_CAP 512

// ============================ device scratch ============================
__device__ float g_Af[(size_t)B_DIM * D_DIM];   // A, MMA-fragment order
__device__ float g_Wf[(size_t)D_DIM * L_DIM];   // W_enc tf32, MMA-fragment order
__device__ float g_Xb[(size_t)B_DIM * D_DIM];   // exact fp32 (xn - pre_bias), row-major
__device__ float g_WT[(size_t)L_DIM * D_DIM];   // W_enc exact transpose, [L][D]
__device__ float g_mu[B_DIM];
__device__ float g_std[B_DIM];
__device__ int   g_tidx[B_DIM * K_TOP];
__device__ float g_tval[B_DIM * K_TOP];

// ============================ helpers ============================
__device__ __forceinline__ uint32_t smem_to_u32(const void* p) {
    uint32_t a;
    asm("{ .reg .u64 t; cvta.to.shared.u64 t, %1; cvt.u32.u64 %0, t; }" : "=r"(a) : "l"(p));
    return a;
}
__device__ __forceinline__ float tf32r(float x) {
    uint32_t u;
    asm("cvt.rna.tf32.f32 %0, %1;" : "=r"(u) : "f"(x));
    return __uint_as_float(u);
}
__device__ __forceinline__ void cp16(uint32_t saddr, const void* g) {
    asm volatile("cp.async.cg.shared.global [%0], [%1], 16;" :: "r"(saddr), "l"(g));
}
#define CP_COMMIT() asm volatile("cp.async.commit_group;" ::: "memory")
#define CP_WAIT0()  asm volatile("cp.async.wait_group 0;" ::: "memory")

__device__ __forceinline__ void mma_tf32(float* d, const uint32_t* a, const uint32_t* b) {
    asm volatile(
        "mma.sync.aligned.m16n8k8.row.col.f32.tf32.tf32.f32 "
        "{%0,%1,%2,%3}, {%4,%5,%6,%7}, {%8,%9}, {%0,%1,%2,%3};"
        : "+f"(d[0]), "+f"(d[1]), "+f"(d[2]), "+f"(d[3])
        : "r"(a[0]), "r"(a[1]), "r"(a[2]), "r"(a[3]), "r"(b[0]), "r"(b[1]));
}

__device__ __forceinline__ float key_to_float(uint32_t k) {
    uint32_t u = (k & 0x80000000u) ? (k & 0x7FFFFFFFu) : ~k;
    return __uint_as_float(u);
}
__device__ __forceinline__ uint32_t float_to_key(float f) {
    uint32_t u = __float_as_uint(f);
    return (u & 0x80000000u) ? ~u : (u | 0x80000000u);
}

// ============================ kernel 1: fused prep ============================
#define WP_KT (D_DIM / 32)        // 24
#define WP_NT (L_DIM / 256)       // 64
#define WP_BLOCKS (WP_KT * WP_NT) // 1536

__global__ void __launch_bounds__(256) prep_kernel(const float* __restrict__ x,
                                                   const float* __restrict__ pre_bias,
                                                   const float* __restrict__ W) {
    __shared__ float sw[32 * 257];
    __shared__ float rs[8], rs2[8], bc[2];
    int bid = blockIdx.x, t = threadIdx.x;

    if (bid < B_DIM) {
        int row = bid;
        const float* xr = x + (size_t)row * D_DIM;
        float v0 = xr[t], v1 = xr[t + 256], v2 = xr[t + 512];
        float s = v0 + v1 + v2;
        float s2 = v0 * v0 + v1 * v1 + v2 * v2;
        for (int o = 16; o; o >>= 1) {
            s  += __shfl_down_sync(0xFFFFFFFFu, s,  o);
            s2 += __shfl_down_sync(0xFFFFFFFFu, s2, o);
        }
        if ((t & 31) == 0) { rs[t >> 5] = s; rs2[t >> 5] = s2; }
        __syncthreads();
        if (t == 0) {
            float a = 0.f, b = 0.f;
            for (int w = 0; w < 8; w++) { a += rs[w]; b += rs2[w]; }
            float mu = a / (float)D_DIM;
            float var = b / (float)D_DIM - mu * mu;
            float sd = sqrtf(fmaxf(var, 0.0f));
            bc[0] = mu; bc[1] = sd;
            g_mu[row] = mu; g_std[row] = sd;
        }
        __syncthreads();
        float mu = bc[0], sd = bc[1];
        float inv = 1.0f / (sd + 1e-5f);
        int p = row >> 7, rloc = row & 127;
        int mb = rloc >> 4, r4 = rloc & 7, hi = (rloc >> 3) & 1;
        size_t pbase = ((size_t)p * 96) * 1024 + (size_t)mb * 128 + (size_t)r4 * 16 + hi;
        float* Xr = g_Xb + (size_t)row * D_DIM;
        #pragma unroll
        for (int j = 0; j < 3; j++) {
            int k = t + j * 256;
            float v = (j == 0 ? v0 : (j == 1 ? v1 : v2));
            float e = (v - mu) * inv - pre_bias[k];
            Xr[k] = e;
            int oct = k >> 3, kl = k & 7, cs = kl & 3, khi = kl >> 2;
            g_Af[pbase + (size_t)oct * 1024 + cs * 4 + 2 * khi] = tf32r(e);
        }
    } else {
        int wb = bid - B_DIM;
        int kt = wb % WP_KT, nt = wb / WP_KT;
        int k0 = kt * 32, n0 = nt * 256;

        #pragma unroll 8
        for (int r = 0; r < 32; r++)
            sw[r * 257 + t] = W[(size_t)(k0 + r) * L_DIM + n0 + t];
        __syncthreads();

        {
            int wrp = t >> 5, ln = t & 31;
            #pragma unroll 8
            for (int i = 0; i < 32; i++) {
                int lcol = wrp * 32 + i;
                g_WT[(size_t)(n0 + lcol) * D_DIM + k0 + ln] = sw[ln * 257 + lcol];
            }
        }

        #pragma unroll
        for (int ol = 0; ol < 4; ol++) {
            int oct = (k0 >> 3) + ol;
            float* out = g_Wf + ((size_t)oct * 2048 + (size_t)nt * 32) * 64;
            #pragma unroll
            for (int j = 0; j < 4; j++) {
                int pr = t * 4 + j;
                int nb8l = pr >> 5, r4 = (pr >> 2) & 7, cs = pr & 3;
                int n = nb8l * 8 + r4;
                out[pr * 2 + 0] = tf32r(sw[(ol * 8 + cs) * 257 + n]);
                out[pr * 2 + 1] = tf32r(sw[(ol * 8 + cs + 4) * 257 + n]);
            }
        }
    }
}

// ============================ kernel 3: persistent encode GEMM ============================
#define KC 64
#define NCHUNK (D_DIM / KC)              // 12
#define STAGE_BYTES 98304
#define B_IN_STAGE 32768
#define GEMM_SMEM (2 * STAGE_BYTES)
#define GEMM_CTAS 148
#define TOT_TILES ((B_DIM / 128) * (L_DIM / 256))   // 4096

__global__ void __launch_bounds__(256, 1) gemm_kernel(const float* __restrict__ lat_bias,
                                                      float* __restrict__ C) {
    extern __shared__ char smem[];
    uint32_t sb = smem_to_u32(smem);
    int t = threadIdx.x, wid = t >> 5, lane = t & 31;
    int wm = wid & 1, wn = wid >> 1;
    int r4 = lane >> 2, cs = lane & 3;

    const int base = TOT_TILES / GEMM_CTAS;
    const int rem  = TOT_TILES % GEMM_CTAS;
    int cta = blockIdx.x;
    int start = (cta < rem) ? cta * (base + 1) : rem * (base + 1) + (cta - rem) * base;
    int ntile = (cta < rem) ? base + 1 : base;
    int gtotal = ntile * NCHUNK;

    auto issue_g = [&](int g) {
        int tl = start + g / NCHUNK;
        int c  = g % NCHUNK;
        int panel = tl >> 6;
        int nb0 = (tl & 63) * 32;
        uint32_t dst = sb + (g & 1) * STAGE_BYTES;
        const float* Asrc = g_Af + ((size_t)panel * 96 + c * 8) * 1024;
        #pragma unroll
        for (int i = 0; i < 8; i++) {
            int idx = t + i * 256;
            cp16(dst + idx * 16, Asrc + idx * 4);
        }
        #pragma unroll
        for (int j = 0; j < 8; j++) {
            const float* Bsrc = g_Wf + ((size_t)(c * 8 + j) * 2048 + nb0) * 64;
            #pragma unroll
            for (int i = 0; i < 2; i++) {
                int idx = t + i * 256;
                cp16(dst + B_IN_STAGE + j * 8192 + idx * 16, Bsrc + idx * 4);
            }
        }
    };

    auto loadFrags = [&](int slot, int k8, uint32_t a[4][4], uint32_t b[8][2]) {
        const float4* Aq = (const float4*)(smem + slot * STAGE_BYTES);
        const float2* Bp = (const float2*)(smem + slot * STAGE_BYTES + B_IN_STAGE);
        #pragma unroll
        for (int mt = 0; mt < 4; mt++) {
            float4 q = Aq[k8 * 256 + (wm * 4 + mt) * 32 + lane];
            a[mt][0] = __float_as_uint(q.x); a[mt][1] = __float_as_uint(q.y);
            a[mt][2] = __float_as_uint(q.z); a[mt][3] = __float_as_uint(q.w);
        }
        #pragma unroll
        for (int nt = 0; nt < 8; nt++) {
            float2 p2 = Bp[k8 * 1024 + (wn * 8 + nt) * 32 + lane];
            b[nt][0] = __float_as_uint(p2.x); b[nt][1] = __float_as_uint(p2.y);
        }
    };

    uint32_t aF[2][4][4], bF[2][8][2];

    issue_g(0); CP_COMMIT();
    CP_WAIT0();
    __syncthreads();
    loadFrags(0, 0, aF[0], bF[0]);

    int pp = 0;
    for (int it = 0; it < ntile; it++) {
        float acc[4][8][4];
        #pragma unroll
        for (int mt = 0; mt < 4; mt++)
            #pragma unroll
            for (int nt = 0; nt < 8; nt++)
                #pragma unroll
                for (int q = 0; q < 4; q++) acc[mt][nt][q] = 0.f;

        for (int c = 0; c < NCHUNK; c++) {
            int gc = it * NCHUNK + c;
            if (gc + 1 < gtotal) { issue_g(gc + 1); CP_COMMIT(); }
            int slot = gc & 1;
            #pragma unroll
            for (int k8 = 0; k8 < 8; k8++) {
                int nxt = pp ^ 1;
                if (k8 < 7) {
                    loadFrags(slot, k8 + 1, aF[nxt], bF[nxt]);
                } else if (gc + 1 < gtotal) {
                    CP_WAIT0();
                    __syncthreads();
                    loadFrags((gc + 1) & 1, 0, aF[nxt], bF[nxt]);
                }
                #pragma unroll
                for (int mt = 0; mt < 4; mt++)
                    #pragma unroll
                    for (int nt = 0; nt < 8; nt++)
                        mma_tf32(acc[mt][nt], aF[pp][mt], bF[pp][nt]);
                pp ^= 1;
            }
        }

        int tl = start + it;
        int m0 = (tl >> 6) * 128, n0 = (tl & 63) * 256;
        #pragma unroll
        for (int mt = 0; mt < 4; mt++) {
            int m = m0 + wm * 64 + mt * 16 + r4;
            #pragma unroll
            for (int nt = 0; nt < 8; nt++) {
                int n = n0 + wn * 64 + nt * 8 + cs * 2;
                float2 bb = *(const float2*)(lat_bias + n);
                float2 v0 = make_float2(acc[mt][nt][0] + bb.x, acc[mt][nt][1] + bb.y);
                float2 v1 = make_float2(acc[mt][nt][2] + bb.x, acc[mt][nt][3] + bb.y);
                *(float2*)(C + (size_t)m * L_DIM + n) = v0;
                *(float2*)(C + (size_t)(m + 8) * L_DIM + n) = v1;
            }
        }
    }
}

// ============================ kernel 4: top-k (vectorized scans) ============================
__global__ void __launch_bounds__(256) topk_kernel(const float* __restrict__ P,
                                                   const float* __restrict__ lat_bias,
                                                   float* __restrict__ latents) {
    __shared__ __align__(16) unsigned short keys16[16384];
    __shared__ float s_redf[8];
    __shared__ int   s_redi[8];
    __shared__ int   s_total;
    __shared__ float s_rms;
    __shared__ int   s_cnt;
    __shared__ int      cand_idx[CAND_CAP];
    __shared__ uint32_t srt_key[CAND_CAP];
    __shared__ int      srt_idx[CAND_CAP];
    __shared__ int      unc_ix[UNC_CAP];
    __shared__ float    unc_ex[UNC_CAP];
    __shared__ int      fin_idx[K_TOP];
    __shared__ float    fin_val[K_TOP];

    int row = blockIdx.x, t = threadIdx.x, lane = t & 31, wid = t >> 5;
    const float* Pr = P + (size_t)row * L_DIM;
    const float4* Pr4 = (const float4*)Pr;
    uint32_t* keysw = (uint32_t*)keys16;

    // ---- load pass: float4 loads, packed key stores, sum of squares ----
    float sum2 = 0.f;
    #pragma unroll 4
    for (int i = 0; i < 16; i++) {
        int q = t + (i << 8);                 // float4 index, 0..4095
        float4 v = Pr4[q];
        uint32_t k0 = float_to_key(v.x) >> 16;
        uint32_t k1 = float_to_key(v.y) >> 16;
        uint32_t k2 = float_to_key(v.z) >> 16;
        uint32_t k3 = float_to_key(v.w) >> 16;
        keysw[q * 2 + 0] = k0 | (k1 << 16);
        keysw[q * 2 + 1] = k2 | (k3 << 16);
        sum2 += v.x * v.x + v.y * v.y + v.z * v.z + v.w * v.w;
    }
    for (int o = 16; o; o >>= 1) sum2 += __shfl_down_sync(0xFFFFFFFFu, sum2, o);
    if (lane == 0) s_redf[wid] = sum2;
    __syncthreads();
    if (t == 0) {
        float a = 0.f;
        for (int w = 0; w < 8; w++) a += s_redf[w];
        s_rms = sqrtf(a / (float)L_DIM);
    }
    __syncthreads();
    float rms = s_rms;

    // ---- threshold count loop (uint2 vector reads: 4 keys per LDS.64) ----
    int T = (int)(float_to_key(2.33f * rms) >> 16);
    int c = 0;
    const uint2* keysv = (const uint2*)keys16;
    for (int iter = 0; iter < 64; iter++) {
        int local = 0;
        #pragma unroll 4
        for (int i = 0; i < 16; i++) {
            uint2 kk = keysv[t + (i << 8)];
            local += (int)((int)(kk.x & 0xFFFFu) >= T) + (int)((int)(kk.x >> 16) >= T)
                   + (int)((int)(kk.y & 0xFFFFu) >= T) + (int)((int)(kk.y >> 16) >= T);
        }
        for (int o = 16; o; o >>= 1) local += __shfl_down_sync(0xFFFFFFFFu, local, o);
        if (lane == 0) s_redi[wid] = local;
        __syncthreads();
        if (t == 0) {
            int tot = 0;
            for (int w = 0; w < 8; w++) tot += s_redi[w];
            s_total = tot;
        }
        __syncthreads();
        c = s_total;
        __syncthreads();
        if (c < K_TOP)            T = (T >= 32) ? T - 32 : 0;
        else if (c > CAND_CAP)    T += 32;
        else break;
        if (T == 0 && c >= K_TOP) break;
    }

    // ---- collect -> sort -> band (<=3 coverage passes) ----
    uint32_t klo = 0, khi = 0;
    for (int pass = 0; pass < 3; pass++) {
        if (t == 0) s_cnt = 0;
        __syncthreads();
        #pragma unroll 2
        for (int i = 0; i < 16; i++) {
            int q = t + (i << 8);
            uint2 kk = keysv[q];
            uint32_t sub0 = kk.x & 0xFFFFu, sub1 = kk.x >> 16;
            uint32_t sub2 = kk.y & 0xFFFFu, sub3 = kk.y >> 16;
            #pragma unroll
            for (int j = 0; j < 4; j++) {
                uint32_t sk = (j == 0) ? sub0 : (j == 1) ? sub1 : (j == 2) ? sub2 : sub3;
                bool p = ((int)sk >= T);
                unsigned m = __ballot_sync(0xFFFFFFFFu, p);
                if (m) {
                    int ldr = __ffs(m) - 1;
                    int bs = 0;
                    if (lane == ldr) bs = atomicAdd(&s_cnt, __popc(m));
                    bs = __shfl_sync(0xFFFFFFFFu, bs, ldr);
                    if (p) {
                        int slot = bs + __popc(m & ((1u << lane) - 1u));
                        if (slot < CAND_CAP) cand_idx[slot] = q * 4 + j;
                    }
                }
            }
        }
        __syncthreads();
        c = s_cnt < CAND_CAP ? s_cnt : CAND_CAP;

        for (int j = t; j < CAND_CAP; j += 256) {
            if (j < c) {
                int idx = cand_idx[j];
                srt_key[j] = float_to_key(Pr[idx]);
                srt_idx[j] = idx;
            } else {
                srt_key[j] = 0u;
                srt_idx[j] = 0x7FFFFFFF;
            }
        }
        __syncthreads();

        for (int k2 = 2; k2 <= CAND_CAP; k2 <<= 1) {
            for (int j2 = k2 >> 1; j2 > 0; j2 >>= 1) {
                for (int i = t; i < CAND_CAP; i += 256) {
                    int ixj = i ^ j2;
                    if (ixj > i) {
                        uint32_t ki = srt_key[i], kj = srt_key[ixj];
                        int ii = srt_idx[i], ij = srt_idx[ixj];
                        bool gt = (ki > kj) || (ki == kj && ii < ij);
                        bool dir = ((i & k2) == 0);
                        if (dir ? !gt : gt) {
                            srt_key[i] = kj; srt_key[ixj] = ki;
                            srt_idx[i] = ij; srt_idx[ixj] = ii;
                        }
                    }
                }
                __syncthreads();
            }
        }

        float v100 = key_to_float(srt_key[K_TOP - 1]);
        klo = float_to_key(v100 - DELTA_BAND);
        khi = float_to_key(v100 + DELTA_BAND);
        if ((int)(klo >> 16) >= T || T == 0) break;
        T = (int)(klo >> 16);
        __syncthreads();
    }

    // ---- band boundaries ----
    {
        int l0 = 0, l1 = 0;
        for (int j = t; j < CAND_CAP; j += 256) {
            l0 += (int)(srt_key[j] > khi);
            l1 += (int)(srt_key[j] >= klo);
        }
        int v = l0;
        for (int o = 16; o; o >>= 1) v += __shfl_down_sync(0xFFFFFFFFu, v, o);
        if (lane == 0) s_redi[wid] = v;
        __syncthreads();
        if (t == 0) { int tot = 0; for (int w = 0; w < 8; w++) tot += s_redi[w]; s_total = tot; }
        __syncthreads();
        l0 = s_total;
        __syncthreads();
        v = l1;
        for (int o = 16; o; o >>= 1) v += __shfl_down_sync(0xFFFFFFFFu, v, o);
        if (lane == 0) s_redi[wid] = v;
        __syncthreads();
        if (t == 0) { int tot = 0; for (int w = 0; w < 8; w++) tot += s_redi[w]; s_total = tot; }
        __syncthreads();
        l1 = s_total;
        __syncthreads();
        if (t == 0) { s_redi[0] = l0; s_redi[1] = l1; }
        __syncthreads();
    }
    int j0 = s_redi[0];
    int j1 = s_redi[1];
    if (j0 > K_TOP - 1) j0 = K_TOP - 1;
    int U = j1 - j0; if (U > UNC_CAP) U = UNC_CAP;
    int need = K_TOP - j0;

    // ---- exact recompute for band members ----
    if (t < U) unc_ix[t] = srt_idx[j0 + t];
    __syncthreads();
    const float* Xr = g_Xb + (size_t)row * D_DIM;
    for (int q = wid; q < U; q += 8) {
        const float* w = g_WT + (size_t)unc_ix[q] * D_DIM;
        float s = 0.f, comp = 0.f;
        for (int d = lane; d < D_DIM; d += 32) {
            float prod = Xr[d] * w[d];
            float tn = s + prod;
            if (fabsf(s) >= fabsf(prod)) comp += (s - tn) + prod;
            else                         comp += (prod - tn) + s;
            s = tn;
        }
        s += comp;
        for (int o = 16; o; o >>= 1) s += __shfl_xor_sync(0xFFFFFFFFu, s, o);
        if (lane == 0) unc_ex[q] = s + lat_bias[unc_ix[q]];
    }
    __syncthreads();

    if (t < j0) { fin_idx[t] = srt_idx[t]; fin_val[t] = key_to_float(srt_key[t]); }
    __syncthreads();
    if (t == 0) {
        for (int a = 1; a < U; a++) {
            float vv = unc_ex[a]; int ii = unc_ix[a]; int b = a - 1;
            while (b >= 0 && (unc_ex[b] < vv || (unc_ex[b] == vv && unc_ix[b] > ii))) {
                unc_ex[b + 1] = unc_ex[b]; unc_ix[b + 1] = unc_ix[b]; b--;
            }
            unc_ex[b + 1] = vv; unc_ix[b + 1] = ii;
        }
        for (int q = 0; q < need; q++) {
            fin_idx[j0 + q] = unc_ix[q]; fin_val[j0 + q] = unc_ex[q];
        }
    }
    __syncthreads();

    // ---- zero-fill the latents row, then scatter ----
    {
        float4 z4 = make_float4(0.f, 0.f, 0.f, 0.f);
        float4* dst = (float4*)(latents + (size_t)row * L_DIM);
        #pragma unroll 4
        for (int i = 0; i < 16; i++) dst[t + (i << 8)] = z4;
    }
    __syncthreads();

    if (t < K_TOP) {
        int my = fin_idx[t]; float v = fin_val[t];
        int r = 0;
        for (int q = 0; q < K_TOP; q++) r += (int)(fin_idx[q] < my);
        g_tidx[row * K_TOP + r] = my;
        g_tval[row * K_TOP + r] = v;
        latents[(size_t)row * L_DIM + my] = v;
    }
}

// ============================ kernel 5: sparse decode ============================
__global__ void __launch_bounds__(256) decode_kernel(const float* __restrict__ Wd,
                                                     const float* __restrict__ pre_bias,
                                                     float* __restrict__ recons) {
    __shared__ int sidx[K_TOP];
    __shared__ float sval[K_TOP];
    int row = blockIdx.x, t = threadIdx.x;
    if (t < K_TOP) { sidx[t] = g_tidx[row * K_TOP + t]; sval[t] = g_tval[row * K_TOP + t]; }
    __syncthreads();
    float a0 = 0.f, a1 = 0.f, a2 = 0.f;
    #pragma unroll 4
    for (int j = 0; j < K_TOP; j++) {
        const float* w = Wd + (size_t)sidx[j] * D_DIM;
        float v = sval[j];
        a0 += v * __ldg(w + t);
        a1 += v * __ldg(w + t + 256);
        a2 += v * __ldg(w + t + 512);
    }
    float sd = g_std[row], mu = g_mu[row];
    float* Rr = recons + (size_t)row * D_DIM;
    Rr[t]       = (a0 + pre_bias[t])       * sd + mu;
    Rr[t + 256] = (a1 + pre_bias[t + 256]) * sd + mu;
    Rr[t + 512] = (a2 + pre_bias[t + 512]) * sd + mu;
}

// ============================ launch ============================
extern "C" void kernel_launch(void* const* d_in, const int* in_sizes, int n_in,
                              void* d_out, int out_size) {
    const float* x        = (const float*)d_in[0];
    const float* pre_bias = (const float*)d_in[1];
    const float* lat_bias = (const float*)d_in[2];
    const float* W_enc    = (const float*)d_in[3];
    const float* W_dec    = (const float*)d_in[4];

    float* outP = (float*)d_out;
    float* outL = outP + (size_t)B_DIM * L_DIM;
    float* outR = outL + (size_t)B_DIM * L_DIM;

    cudaFuncSetAttribute(gemm_kernel, cudaFuncAttributeMaxDynamicSharedMemorySize, GEMM_SMEM);

    prep_kernel<<<B_DIM + WP_BLOCKS, 256>>>(x, pre_bias, W_enc);
    gemm_kernel<<<GEMM_CTAS, 256, GEMM_SMEM>>>(lat_bias, outP);
    topk_kernel<<<B_DIM, 256>>>(outP, lat_bias, outL);
    decode_kernel<<<B_DIM, 256>>>(W_dec, pre_bias, outR);
}

// round 16
// speedup vs baseline: 1.6009x; 1.0109x over previous
#include <cuda_runtime.h>
#include <cstdint>

#define B_DIM 8192
#define D_DIM 768
#define L_DIM 16384
#define K_TOP 100
#define DELTA_BAND 2.5e-3f
#define UNC_CAP 192
#define CAND_CAP 512

// ============================ device scratch ============================
__device__ float g_Af[(size_t)B_DIM * D_DIM];   // A, MMA-fragment order
__device__ float g_Wf[(size_t)D_DIM * L_DIM];   // W_enc tf32, MMA-fragment order
__device__ float g_Xb[(size_t)B_DIM * D_DIM];   // exact fp32 (xn - pre_bias), row-major
__device__ float g_WT[(size_t)L_DIM * D_DIM];   // W_enc exact transpose, [L][D]
__device__ float g_mu[B_DIM];
__device__ float g_std[B_DIM];
__device__ int   g_tidx[B_DIM * K_TOP];
__device__ float g_tval[B_DIM * K_TOP];

// ============================ helpers ============================
__device__ __forceinline__ uint32_t smem_to_u32(const void* p) {
    uint32_t a;
    asm("{ .reg .u64 t; cvta.to.shared.u64 t, %1; cvt.u32.u64 %0, t; }" : "=r"(a) : "l"(p));
    return a;
}
__device__ __forceinline__ float tf32r(float x) {
    uint32_t u;
    asm("cvt.rna.tf32.f32 %0, %1;" : "=r"(u) : "f"(x));
    return __uint_as_float(u);
}
__device__ __forceinline__ void cp16(uint32_t saddr, const void* g) {
    asm volatile("cp.async.cg.shared.global [%0], [%1], 16;" :: "r"(saddr), "l"(g));
}
#define CP_COMMIT() asm volatile("cp.async.commit_group;" ::: "memory")
#define CP_WAIT0()  asm volatile("cp.async.wait_group 0;" ::: "memory")

__device__ __forceinline__ void mma_tf32(float* d, const uint32_t* a, const uint32_t* b) {
    asm volatile(
        "mma.sync.aligned.m16n8k8.row.col.f32.tf32.tf32.f32 "
        "{%0,%1,%2,%3}, {%4,%5,%6,%7}, {%8,%9}, {%0,%1,%2,%3};"
        : "+f"(d[0]), "+f"(d[1]), "+f"(d[2]), "+f"(d[3])
        : "r"(a[0]), "r"(a[1]), "r"(a[2]), "r"(a[3]), "r"(b[0]), "r"(b[1]));
}

__device__ __forceinline__ float key_to_float(uint32_t k) {
    uint32_t u = (k & 0x80000000u) ? (k & 0x7FFFFFFFu) : ~k;
    return __uint_as_float(u);
}
__device__ __forceinline__ uint32_t float_to_key(float f) {
    uint32_t u = __float_as_uint(f);
    return (u & 0x80000000u) ? ~u : (u | 0x80000000u);
}

// ============================ kernel 1: fused prep ============================
#define WP_KT (D_DIM / 32)        // 24
#define WP_NT (L_DIM / 256)       // 64
#define WP_BLOCKS (WP_KT * WP_NT) // 1536

__global__ void __launch_bounds__(256) prep_kernel(const float* __restrict__ x,
                                                   const float* __restrict__ pre_bias,
                                                   const float* __restrict__ W) {
    __shared__ float sw[32 * 257];
    __shared__ float rs[8], rs2[8], bc[2];
    int bid = blockIdx.x, t = threadIdx.x;

    if (bid < B_DIM) {
        int row = bid;
        const float* xr = x + (size_t)row * D_DIM;
        float v0 = xr[t], v1 = xr[t + 256], v2 = xr[t + 512];
        float s = v0 + v1 + v2;
        float s2 = v0 * v0 + v1 * v1 + v2 * v2;
        for (int o = 16; o; o >>= 1) {
            s  += __shfl_down_sync(0xFFFFFFFFu, s,  o);
            s2 += __shfl_down_sync(0xFFFFFFFFu, s2, o);
        }
        if ((t & 31) == 0) { rs[t >> 5] = s; rs2[t >> 5] = s2; }
        __syncthreads();
        if (t == 0) {
            float a = 0.f, b = 0.f;
            for (int w = 0; w < 8; w++) { a += rs[w]; b += rs2[w]; }
            float mu = a / (float)D_DIM;
            float var = b / (float)D_DIM - mu * mu;
            float sd = sqrtf(fmaxf(var, 0.0f));
            bc[0] = mu; bc[1] = sd;
            g_mu[row] = mu; g_std[row] = sd;
        }
        __syncthreads();
        float mu = bc[0], sd = bc[1];
        float inv = 1.0f / (sd + 1e-5f);
        int p = row >> 7, rloc = row & 127;
        int mb = rloc >> 4, r4 = rloc & 7, hi = (rloc >> 3) & 1;
        size_t pbase = ((size_t)p * 96) * 1024 + (size_t)mb * 128 + (size_t)r4 * 16 + hi;
        float* Xr = g_Xb + (size_t)row * D_DIM;
        #pragma unroll
        for (int j = 0; j < 3; j++) {
            int k = t + j * 256;
            float v = (j == 0 ? v0 : (j == 1 ? v1 : v2));
            float e = (v - mu) * inv - pre_bias[k];
            Xr[k] = e;
            int oct = k >> 3, kl = k & 7, cs = kl & 3, khi = kl >> 2;
            g_Af[pbase + (size_t)oct * 1024 + cs * 4 + 2 * khi] = tf32r(e);
        }
    } else {
        int wb = bid - B_DIM;
        int kt = wb % WP_KT, nt = wb / WP_KT;
        int k0 = kt * 32, n0 = nt * 256;

        #pragma unroll 8
        for (int r = 0; r < 32; r++)
            sw[r * 257 + t] = W[(size_t)(k0 + r) * L_DIM + n0 + t];
        __syncthreads();

        {
            int wrp = t >> 5, ln = t & 31;
            #pragma unroll 8
            for (int i = 0; i < 32; i++) {
                int lcol = wrp * 32 + i;
                g_WT[(size_t)(n0 + lcol) * D_DIM + k0 + ln] = sw[ln * 257 + lcol];
            }
        }

        #pragma unroll
        for (int ol = 0; ol < 4; ol++) {
            int oct = (k0 >> 3) + ol;
            float* out = g_Wf + ((size_t)oct * 2048 + (size_t)nt * 32) * 64;
            #pragma unroll
            for (int j = 0; j < 4; j++) {
                int pr = t * 4 + j;
                int nb8l = pr >> 5, r4 = (pr >> 2) & 7, cs = pr & 3;
                int n = nb8l * 8 + r4;
                out[pr * 2 + 0] = tf32r(sw[(ol * 8 + cs) * 257 + n]);
                out[pr * 2 + 1] = tf32r(sw[(ol * 8 + cs + 4) * 257 + n]);
            }
        }
    }
}

// ============================ kernel 3: persistent encode GEMM ============================
#define KC 64
#define NCHUNK (D_DIM / KC)              // 12
#define STAGE_BYTES 98304
#define B_IN_STAGE 32768
#define GEMM_SMEM (2 * STAGE_BYTES)
#define GEMM_CTAS 148
#define TOT_TILES ((B_DIM / 128) * (L_DIM / 256))   // 4096

__global__ void __launch_bounds__(256, 1) gemm_kernel(const float* __restrict__ lat_bias,
                                                      float* __restrict__ C) {
    extern __shared__ char smem[];
    uint32_t sb = smem_to_u32(smem);
    int t = threadIdx.x, wid = t >> 5, lane = t & 31;
    int wm = wid & 1, wn = wid >> 1;
    int r4 = lane >> 2, cs = lane & 3;

    const int base = TOT_TILES / GEMM_CTAS;
    const int rem  = TOT_TILES % GEMM_CTAS;
    int cta = blockIdx.x;
    int start = (cta < rem) ? cta * (base + 1) : rem * (base + 1) + (cta - rem) * base;
    int ntile = (cta < rem) ? base + 1 : base;
    int gtotal = ntile * NCHUNK;

    auto issue_g = [&](int g) {
        int tl = start + g / NCHUNK;
        int c  = g % NCHUNK;
        int panel = tl >> 6;
        int nb0 = (tl & 63) * 32;
        uint32_t dst = sb + (g & 1) * STAGE_BYTES;
        const float* Asrc = g_Af + ((size_t)panel * 96 + c * 8) * 1024;
        #pragma unroll
        for (int i = 0; i < 8; i++) {
            int idx = t + i * 256;
            cp16(dst + idx * 16, Asrc + idx * 4);
        }
        #pragma unroll
        for (int j = 0; j < 8; j++) {
            const float* Bsrc = g_Wf + ((size_t)(c * 8 + j) * 2048 + nb0) * 64;
            #pragma unroll
            for (int i = 0; i < 2; i++) {
                int idx = t + i * 256;
                cp16(dst + B_IN_STAGE + j * 8192 + idx * 16, Bsrc + idx * 4);
            }
        }
    };

    auto loadFrags = [&](int slot, int k8, uint32_t a[4][4], uint32_t b[8][2]) {
        const float4* Aq = (const float4*)(smem + slot * STAGE_BYTES);
        const float2* Bp = (const float2*)(smem + slot * STAGE_BYTES + B_IN_STAGE);
        #pragma unroll
        for (int mt = 0; mt < 4; mt++) {
            float4 q = Aq[k8 * 256 + (wm * 4 + mt) * 32 + lane];
            a[mt][0] = __float_as_uint(q.x); a[mt][1] = __float_as_uint(q.y);
            a[mt][2] = __float_as_uint(q.z); a[mt][3] = __float_as_uint(q.w);
        }
        #pragma unroll
        for (int nt = 0; nt < 8; nt++) {
            float2 p2 = Bp[k8 * 1024 + (wn * 8 + nt) * 32 + lane];
            b[nt][0] = __float_as_uint(p2.x); b[nt][1] = __float_as_uint(p2.y);
        }
    };

    uint32_t aF[2][4][4], bF[2][8][2];

    issue_g(0); CP_COMMIT();
    CP_WAIT0();
    __syncthreads();
    loadFrags(0, 0, aF[0], bF[0]);

    int pp = 0;
    for (int it = 0; it < ntile; it++) {
        float acc[4][8][4];
        #pragma unroll
        for (int mt = 0; mt < 4; mt++)
            #pragma unroll
            for (int nt = 0; nt < 8; nt++)
                #pragma unroll
                for (int q = 0; q < 4; q++) acc[mt][nt][q] = 0.f;

        for (int c = 0; c < NCHUNK; c++) {
            int gc = it * NCHUNK + c;
            if (gc + 1 < gtotal) { issue_g(gc + 1); CP_COMMIT(); }
            int slot = gc & 1;
            #pragma unroll
            for (int k8 = 0; k8 < 8; k8++) {
                int nxt = pp ^ 1;
                if (k8 < 7) {
                    loadFrags(slot, k8 + 1, aF[nxt], bF[nxt]);
                } else if (gc + 1 < gtotal) {
                    CP_WAIT0();
                    __syncthreads();
                    loadFrags((gc + 1) & 1, 0, aF[nxt], bF[nxt]);
                }
                #pragma unroll
                for (int mt = 0; mt < 4; mt++)
                    #pragma unroll
                    for (int nt = 0; nt < 8; nt++)
                        mma_tf32(acc[mt][nt], aF[pp][mt], bF[pp][nt]);
                pp ^= 1;
            }
        }

        int tl = start + it;
        int m0 = (tl >> 6) * 128, n0 = (tl & 63) * 256;
        #pragma unroll
        for (int mt = 0; mt < 4; mt++) {
            int m = m0 + wm * 64 + mt * 16 + r4;
            #pragma unroll
            for (int nt = 0; nt < 8; nt++) {
                int n = n0 + wn * 64 + nt * 8 + cs * 2;
                float2 bb = *(const float2*)(lat_bias + n);
                float2 v0 = make_float2(acc[mt][nt][0] + bb.x, acc[mt][nt][1] + bb.y);
                float2 v1 = make_float2(acc[mt][nt][2] + bb.x, acc[mt][nt][3] + bb.y);
                *(float2*)(C + (size_t)m * L_DIM + n) = v0;
                *(float2*)(C + (size_t)(m + 8) * L_DIM + n) = v1;
            }
        }
    }
}

// ============================ kernel 4: top-k (collect-first, vectorized) ============================
__global__ void __launch_bounds__(256) topk_kernel(const float* __restrict__ P,
                                                   const float* __restrict__ lat_bias,
                                                   float* __restrict__ latents) {
    __shared__ __align__(16) unsigned short keys16[16384];
    __shared__ float s_redf[8];
    __shared__ int   s_redi[8];
    __shared__ int   s_total;
    __shared__ float s_rms;
    __shared__ int   s_cnt;
    __shared__ int      cand_idx[CAND_CAP];
    __shared__ uint32_t srt_key[CAND_CAP];
    __shared__ int      srt_idx[CAND_CAP];
    __shared__ int      unc_ix[UNC_CAP];
    __shared__ float    unc_ex[UNC_CAP];
    __shared__ int      fin_idx[K_TOP];
    __shared__ float    fin_val[K_TOP];

    int row = blockIdx.x, t = threadIdx.x, lane = t & 31, wid = t >> 5;
    const float* Pr = P + (size_t)row * L_DIM;
    const float4* Pr4 = (const float4*)Pr;
    uint32_t* keysw = (uint32_t*)keys16;
    const uint2* keysv = (const uint2*)keys16;

    // ---- load pass: float4 loads, packed key stores, sum of squares ----
    float sum2 = 0.f;
    #pragma unroll 4
    for (int i = 0; i < 16; i++) {
        int q = t + (i << 8);
        float4 v = Pr4[q];
        uint32_t k0 = float_to_key(v.x) >> 16;
        uint32_t k1 = float_to_key(v.y) >> 16;
        uint32_t k2 = float_to_key(v.z) >> 16;
        uint32_t k3 = float_to_key(v.w) >> 16;
        keysw[q * 2 + 0] = k0 | (k1 << 16);
        keysw[q * 2 + 1] = k2 | (k3 << 16);
        sum2 += v.x * v.x + v.y * v.y + v.z * v.z + v.w * v.w;
    }
    for (int o = 16; o; o >>= 1) sum2 += __shfl_down_sync(0xFFFFFFFFu, sum2, o);
    if (lane == 0) s_redf[wid] = sum2;
    __syncthreads();
    if (t == 0) {
        float a = 0.f;
        for (int w = 0; w < 8; w++) a += s_redf[w];
        s_rms = sqrtf(a / (float)L_DIM);
    }
    __syncthreads();
    float rms = s_rms;

    int T = (int)(float_to_key(2.33f * rms) >> 16);
    uint32_t klo = 0, khi = 0;
    int c = 0;

    // collect-first loop; verify count after collecting; adjust T only if needed
    for (int attempt = 0; attempt < 8; attempt++) {
        if (t == 0) s_cnt = 0;
        __syncthreads();
        #pragma unroll 2
        for (int i = 0; i < 16; i++) {
            int q = t + (i << 8);
            uint2 kk = keysv[q];
            uint32_t sub0 = kk.x & 0xFFFFu, sub1 = kk.x >> 16;
            uint32_t sub2 = kk.y & 0xFFFFu, sub3 = kk.y >> 16;
            #pragma unroll
            for (int j = 0; j < 4; j++) {
                uint32_t sk = (j == 0) ? sub0 : (j == 1) ? sub1 : (j == 2) ? sub2 : sub3;
                bool p = ((int)sk >= T);
                unsigned m = __ballot_sync(0xFFFFFFFFu, p);
                if (m) {
                    int ldr = __ffs(m) - 1;
                    int bs = 0;
                    if (lane == ldr) bs = atomicAdd(&s_cnt, __popc(m));
                    bs = __shfl_sync(0xFFFFFFFFu, bs, ldr);
                    if (p) {
                        int slot = bs + __popc(m & ((1u << lane) - 1u));
                        if (slot < CAND_CAP) cand_idx[slot] = q * 4 + j;
                    }
                }
            }
        }
        __syncthreads();
        int raw = s_cnt;
        __syncthreads();
        if (raw < K_TOP)        { T = (T >= 32) ? T - 32 : 0; if (raw >= K_TOP || T > 0) continue; }
        else if (raw > CAND_CAP) { T += 32; continue; }
        c = raw < CAND_CAP ? raw : CAND_CAP;

        // fetch exact values for candidates; pad
        for (int j = t; j < CAND_CAP; j += 256) {
            if (j < c) {
                int idx = cand_idx[j];
                srt_key[j] = float_to_key(Pr[idx]);
                srt_idx[j] = idx;
            } else {
                srt_key[j] = 0u;
                srt_idx[j] = 0x7FFFFFFF;
            }
        }
        __syncthreads();

        // bitonic sort 512: (key desc, idx asc)
        for (int k2 = 2; k2 <= CAND_CAP; k2 <<= 1) {
            for (int j2 = k2 >> 1; j2 > 0; j2 >>= 1) {
                for (int i = t; i < CAND_CAP; i += 256) {
                    int ixj = i ^ j2;
                    if (ixj > i) {
                        uint32_t ki = srt_key[i], kj = srt_key[ixj];
                        int ii = srt_idx[i], ij = srt_idx[ixj];
                        bool gt = (ki > kj) || (ki == kj && ii < ij);
                        bool dir = ((i & k2) == 0);
                        if (dir ? !gt : gt) {
                            srt_key[i] = kj; srt_key[ixj] = ki;
                            srt_idx[i] = ij; srt_idx[ixj] = ii;
                        }
                    }
                }
                __syncthreads();
            }
        }

        float v100 = key_to_float(srt_key[K_TOP - 1]);
        klo = float_to_key(v100 - DELTA_BAND);
        khi = float_to_key(v100 + DELTA_BAND);
        if ((int)(klo >> 16) >= T || T == 0) break;   // band covered
        T = (int)(klo >> 16);
        __syncthreads();
    }

    // ---- band boundaries ----
    {
        int l0 = 0, l1 = 0;
        for (int j = t; j < CAND_CAP; j += 256) {
            l0 += (int)(srt_key[j] > khi);
            l1 += (int)(srt_key[j] >= klo);
        }
        int v = l0;
        for (int o = 16; o; o >>= 1) v += __shfl_down_sync(0xFFFFFFFFu, v, o);
        if (lane == 0) s_redi[wid] = v;
        __syncthreads();
        if (t == 0) { int tot = 0; for (int w = 0; w < 8; w++) tot += s_redi[w]; s_total = tot; }
        __syncthreads();
        l0 = s_total;
        __syncthreads();
        v = l1;
        for (int o = 16; o; o >>= 1) v += __shfl_down_sync(0xFFFFFFFFu, v, o);
        if (lane == 0) s_redi[wid] = v;
        __syncthreads();
        if (t == 0) { int tot = 0; for (int w = 0; w < 8; w++) tot += s_redi[w]; s_total = tot; }
        __syncthreads();
        l1 = s_total;
        __syncthreads();
        if (t == 0) { s_redi[0] = l0; s_redi[1] = l1; }
        __syncthreads();
    }
    int j0 = s_redi[0];
    int j1 = s_redi[1];
    if (j0 > K_TOP - 1) j0 = K_TOP - 1;
    int U = j1 - j0; if (U > UNC_CAP) U = UNC_CAP;
    int need = K_TOP - j0;

    if (t < U) unc_ix[t] = srt_idx[j0 + t];
    __syncthreads();

    // ---- zero-fill the latents row NOW (stores drain under the exact dots) ----
    {
        float4 z4 = make_float4(0.f, 0.f, 0.f, 0.f);
        float4* dst = (float4*)(latents + (size_t)row * L_DIM);
        #pragma unroll 4
        for (int i = 0; i < 16; i++) dst[t + (i << 8)] = z4;
    }

    // ---- exact recompute for band members ----
    const float* Xr = g_Xb + (size_t)row * D_DIM;
    for (int q = wid; q < U; q += 8) {
        const float* w = g_WT + (size_t)unc_ix[q] * D_DIM;
        float s = 0.f, comp = 0.f;
        for (int d = lane; d < D_DIM; d += 32) {
            float prod = Xr[d] * w[d];
            float tn = s + prod;
            if (fabsf(s) >= fabsf(prod)) comp += (s - tn) + prod;
            else                         comp += (prod - tn) + s;
            s = tn;
        }
        s += comp;
        for (int o = 16; o; o >>= 1) s += __shfl_xor_sync(0xFFFFFFFFu, s, o);
        if (lane == 0) unc_ex[q] = s + lat_bias[unc_ix[q]];
    }
    __syncthreads();

    if (t < j0) { fin_idx[t] = srt_idx[t]; fin_val[t] = key_to_float(srt_key[t]); }
    __syncthreads();
    if (t == 0) {
        for (int a = 1; a < U; a++) {
            float vv = unc_ex[a]; int ii = unc_ix[a]; int b = a - 1;
            while (b >= 0 && (unc_ex[b] < vv || (unc_ex[b] == vv && unc_ix[b] > ii))) {
                unc_ex[b + 1] = unc_ex[b]; unc_ix[b + 1] = unc_ix[b]; b--;
            }
            unc_ex[b + 1] = vv; unc_ix[b + 1] = ii;
        }
        for (int q = 0; q < need; q++) {
            fin_idx[j0 + q] = unc_ix[q]; fin_val[j0 + q] = unc_ex[q];
        }
    }
    __syncthreads();   // zero-stores from this block are also complete (same threads)

    if (t < K_TOP) {
        int my = fin_idx[t]; float v = fin_val[t];
        int r = 0;
        for (int q = 0; q < K_TOP; q++) r += (int)(fin_idx[q] < my);
        g_tidx[row * K_TOP + r] = my;
        g_tval[row * K_TOP + r] = v;
        latents[(size_t)row * L_DIM + my] = v;
    }
}

// ============================ kernel 5: sparse decode ============================
__global__ void __launch_bounds__(256) decode_kernel(const float* __restrict__ Wd,
                                                     const float* __restrict__ pre_bias,
                                                     float* __restrict__ recons) {
    __shared__ int sidx[K_TOP];
    __shared__ float sval[K_TOP];
    int row = blockIdx.x, t = threadIdx.x;
    if (t < K_TOP) { sidx[t] = g_tidx[row * K_TOP + t]; sval[t] = g_tval[row * K_TOP + t]; }
    __syncthreads();
    float a0 = 0.f, a1 = 0.f, a2 = 0.f;
    #pragma unroll 4
    for (int j = 0; j < K_TOP; j++) {
        const float* w = Wd + (size_t)sidx[j] * D_DIM;
        float v = sval[j];
        a0 += v * __ldg(w + t);
        a1 += v * __ldg(w + t + 256);
        a2 += v * __ldg(w + t + 512);
    }
    float sd = g_std[row], mu = g_mu[row];
    float* Rr = recons + (size_t)row * D_DIM;
    Rr[t]       = (a0 + pre_bias[t])       * sd + mu;
    Rr[t + 256] = (a1 + pre_bias[t + 256]) * sd + mu;
    Rr[t + 512] = (a2 + pre_bias[t + 512]) * sd + mu;
}

// ============================ launch ============================
extern "C" void kernel_launch(void* const* d_in, const int* in_sizes, int n_in,
                              void* d_out, int out_size) {
    const float* x        = (const float*)d_in[0];
    const float* pre_bias = (const float*)d_in[1];
    const float* lat_bias = (const float*)d_in[2];
    const float* W_enc    = (const float*)d_in[3];
    const float* W_dec    = (const float*)d_in[4];

    float* outP = (float*)d_out;
    float* outL = outP + (size_t)B_DIM * L_DIM;
    float* outR = outL + (size_t)B_DIM * L_DIM;

    cudaFuncSetAttribute(gemm_kernel, cudaFuncAttributeMaxDynamicSharedMemorySize, GEMM_SMEM);

    prep_kernel<<<B_DIM + WP_BLOCKS, 256>>>(x, pre_bias, W_enc);
    gemm_kernel<<<GEMM_CTAS, 256, GEMM_SMEM>>>(lat_bias, outP);
    topk_kernel<<<B_DIM, 256>>>(outP, lat_bias, outL);
    decode_kernel<<<B_DIM, 256>>>(W_dec, pre_bias, outR);
}

// round 17
// speedup vs baseline: 1.6367x; 1.0224x over previous
#include <cuda_runtime.h>
#include <cstdint>

#define B_DIM 8192
#define D_DIM 768
#define L_DIM 16384
#define K_TOP 100
#define DELTA_BAND 2.5e-3f
#define UNC_CAP 192
#define CAND_CAP 512
#define HIT_CAP 8

// ============================ device scratch ============================
__device__ float g_Af[(size_t)B_DIM * D_DIM];   // A, MMA-fragment order
__device__ float g_Wf[(size_t)D_DIM * L_DIM];   // W_enc tf32, MMA-fragment order
__device__ float g_Xb[(size_t)B_DIM * D_DIM];   // exact fp32 (xn - pre_bias), row-major
__device__ float g_WT[(size_t)L_DIM * D_DIM];   // W_enc exact transpose, [L][D]
__device__ float g_mu[B_DIM];
__device__ float g_std[B_DIM];
__device__ int   g_tidx[B_DIM * K_TOP];
__device__ float g_tval[B_DIM * K_TOP];

// ============================ helpers ============================
__device__ __forceinline__ uint32_t smem_to_u32(const void* p) {
    uint32_t a;
    asm("{ .reg .u64 t; cvta.to.shared.u64 t, %1; cvt.u32.u64 %0, t; }" : "=r"(a) : "l"(p));
    return a;
}
__device__ __forceinline__ float tf32r(float x) {
    uint32_t u;
    asm("cvt.rna.tf32.f32 %0, %1;" : "=r"(u) : "f"(x));
    return __uint_as_float(u);
}
__device__ __forceinline__ void cp16(uint32_t saddr, const void* g) {
    asm volatile("cp.async.cg.shared.global [%0], [%1], 16;" :: "r"(saddr), "l"(g));
}
#define CP_COMMIT() asm volatile("cp.async.commit_group;" ::: "memory")
#define CP_WAIT0()  asm volatile("cp.async.wait_group 0;" ::: "memory")

__device__ __forceinline__ void mma_tf32(float* d, const uint32_t* a, const uint32_t* b) {
    asm volatile(
        "mma.sync.aligned.m16n8k8.row.col.f32.tf32.tf32.f32 "
        "{%0,%1,%2,%3}, {%4,%5,%6,%7}, {%8,%9}, {%0,%1,%2,%3};"
        : "+f"(d[0]), "+f"(d[1]), "+f"(d[2]), "+f"(d[3])
        : "r"(a[0]), "r"(a[1]), "r"(a[2]), "r"(a[3]), "r"(b[0]), "r"(b[1]));
}

__device__ __forceinline__ float key_to_float(uint32_t k) {
    uint32_t u = (k & 0x80000000u) ? (k & 0x7FFFFFFFu) : ~k;
    return __uint_as_float(u);
}
__device__ __forceinline__ uint32_t float_to_key(float f) {
    uint32_t u = __float_as_uint(f);
    return (u & 0x80000000u) ? ~u : (u | 0x80000000u);
}

// ============================ kernel 1: fused prep ============================
#define WP_KT (D_DIM / 32)        // 24
#define WP_NT (L_DIM / 256)       // 64
#define WP_BLOCKS (WP_KT * WP_NT) // 1536

__global__ void __launch_bounds__(256) prep_kernel(const float* __restrict__ x,
                                                   const float* __restrict__ pre_bias,
                                                   const float* __restrict__ W) {
    __shared__ float sw[32 * 257];
    __shared__ float rs[8], rs2[8], bc[2];
    int bid = blockIdx.x, t = threadIdx.x;

    if (bid < B_DIM) {
        int row = bid;
        const float* xr = x + (size_t)row * D_DIM;
        float v0 = xr[t], v1 = xr[t + 256], v2 = xr[t + 512];
        float s = v0 + v1 + v2;
        float s2 = v0 * v0 + v1 * v1 + v2 * v2;
        for (int o = 16; o; o >>= 1) {
            s  += __shfl_down_sync(0xFFFFFFFFu, s,  o);
            s2 += __shfl_down_sync(0xFFFFFFFFu, s2, o);
        }
        if ((t & 31) == 0) { rs[t >> 5] = s; rs2[t >> 5] = s2; }
        __syncthreads();
        if (t == 0) {
            float a = 0.f, b = 0.f;
            for (int w = 0; w < 8; w++) { a += rs[w]; b += rs2[w]; }
            float mu = a / (float)D_DIM;
            float var = b / (float)D_DIM - mu * mu;
            float sd = sqrtf(fmaxf(var, 0.0f));
            bc[0] = mu; bc[1] = sd;
            g_mu[row] = mu; g_std[row] = sd;
        }
        __syncthreads();
        float mu = bc[0], sd = bc[1];
        float inv = 1.0f / (sd + 1e-5f);
        int p = row >> 7, rloc = row & 127;
        int mb = rloc >> 4, r4 = rloc & 7, hi = (rloc >> 3) & 1;
        size_t pbase = ((size_t)p * 96) * 1024 + (size_t)mb * 128 + (size_t)r4 * 16 + hi;
        float* Xr = g_Xb + (size_t)row * D_DIM;
        #pragma unroll
        for (int j = 0; j < 3; j++) {
            int k = t + j * 256;
            float v = (j == 0 ? v0 : (j == 1 ? v1 : v2));
            float e = (v - mu) * inv - pre_bias[k];
            Xr[k] = e;
            int oct = k >> 3, kl = k & 7, cs = kl & 3, khi = kl >> 2;
            g_Af[pbase + (size_t)oct * 1024 + cs * 4 + 2 * khi] = tf32r(e);
        }
    } else {
        int wb = bid - B_DIM;
        int kt = wb % WP_KT, nt = wb / WP_KT;
        int k0 = kt * 32, n0 = nt * 256;

        #pragma unroll 8
        for (int r = 0; r < 32; r++)
            sw[r * 257 + t] = W[(size_t)(k0 + r) * L_DIM + n0 + t];
        __syncthreads();

        {
            int wrp = t >> 5, ln = t & 31;
            #pragma unroll 8
            for (int i = 0; i < 32; i++) {
                int lcol = wrp * 32 + i;
                g_WT[(size_t)(n0 + lcol) * D_DIM + k0 + ln] = sw[ln * 257 + lcol];
            }
        }

        #pragma unroll
        for (int ol = 0; ol < 4; ol++) {
            int oct = (k0 >> 3) + ol;
            float* out = g_Wf + ((size_t)oct * 2048 + (size_t)nt * 32) * 64;
            #pragma unroll
            for (int j = 0; j < 4; j++) {
                int pr = t * 4 + j;
                int nb8l = pr >> 5, r4 = (pr >> 2) & 7, cs = pr & 3;
                int n = nb8l * 8 + r4;
                out[pr * 2 + 0] = tf32r(sw[(ol * 8 + cs) * 257 + n]);
                out[pr * 2 + 1] = tf32r(sw[(ol * 8 + cs + 4) * 257 + n]);
            }
        }
    }
}

// ============================ kernel 3: persistent encode GEMM ============================
#define KC 64
#define NCHUNK (D_DIM / KC)              // 12
#define STAGE_BYTES 98304
#define B_IN_STAGE 32768
#define GEMM_SMEM (2 * STAGE_BYTES)
#define GEMM_CTAS 148
#define TOT_TILES ((B_DIM / 128) * (L_DIM / 256))   // 4096

__global__ void __launch_bounds__(256, 1) gemm_kernel(const float* __restrict__ lat_bias,
                                                      float* __restrict__ C) {
    extern __shared__ char smem[];
    uint32_t sb = smem_to_u32(smem);
    int t = threadIdx.x, wid = t >> 5, lane = t & 31;
    int wm = wid & 1, wn = wid >> 1;
    int r4 = lane >> 2, cs = lane & 3;

    const int base = TOT_TILES / GEMM_CTAS;
    const int rem  = TOT_TILES % GEMM_CTAS;
    int cta = blockIdx.x;
    int start = (cta < rem) ? cta * (base + 1) : rem * (base + 1) + (cta - rem) * base;
    int ntile = (cta < rem) ? base + 1 : base;
    int gtotal = ntile * NCHUNK;

    auto issue_g = [&](int g) {
        int tl = start + g / NCHUNK;
        int c  = g % NCHUNK;
        int panel = tl >> 6;
        int nb0 = (tl & 63) * 32;
        uint32_t dst = sb + (g & 1) * STAGE_BYTES;
        const float* Asrc = g_Af + ((size_t)panel * 96 + c * 8) * 1024;
        #pragma unroll
        for (int i = 0; i < 8; i++) {
            int idx = t + i * 256;
            cp16(dst + idx * 16, Asrc + idx * 4);
        }
        #pragma unroll
        for (int j = 0; j < 8; j++) {
            const float* Bsrc = g_Wf + ((size_t)(c * 8 + j) * 2048 + nb0) * 64;
            #pragma unroll
            for (int i = 0; i < 2; i++) {
                int idx = t + i * 256;
                cp16(dst + B_IN_STAGE + j * 8192 + idx * 16, Bsrc + idx * 4);
            }
        }
    };

    auto loadFrags = [&](int slot, int k8, uint32_t a[4][4], uint32_t b[8][2]) {
        const float4* Aq = (const float4*)(smem + slot * STAGE_BYTES);
        const float2* Bp = (const float2*)(smem + slot * STAGE_BYTES + B_IN_STAGE);
        #pragma unroll
        for (int mt = 0; mt < 4; mt++) {
            float4 q = Aq[k8 * 256 + (wm * 4 + mt) * 32 + lane];
            a[mt][0] = __float_as_uint(q.x); a[mt][1] = __float_as_uint(q.y);
            a[mt][2] = __float_as_uint(q.z); a[mt][3] = __float_as_uint(q.w);
        }
        #pragma unroll
        for (int nt = 0; nt < 8; nt++) {
            float2 p2 = Bp[k8 * 1024 + (wn * 8 + nt) * 32 + lane];
            b[nt][0] = __float_as_uint(p2.x); b[nt][1] = __float_as_uint(p2.y);
        }
    };

    uint32_t aF[2][4][4], bF[2][8][2];

    issue_g(0); CP_COMMIT();
    CP_WAIT0();
    __syncthreads();
    loadFrags(0, 0, aF[0], bF[0]);

    int pp = 0;
    for (int it = 0; it < ntile; it++) {
        float acc[4][8][4];
        #pragma unroll
        for (int mt = 0; mt < 4; mt++)
            #pragma unroll
            for (int nt = 0; nt < 8; nt++)
                #pragma unroll
                for (int q = 0; q < 4; q++) acc[mt][nt][q] = 0.f;

        for (int c = 0; c < NCHUNK; c++) {
            int gc = it * NCHUNK + c;
            if (gc + 1 < gtotal) { issue_g(gc + 1); CP_COMMIT(); }
            int slot = gc & 1;
            #pragma unroll
            for (int k8 = 0; k8 < 8; k8++) {
                int nxt = pp ^ 1;
                if (k8 < 7) {
                    loadFrags(slot, k8 + 1, aF[nxt], bF[nxt]);
                } else if (gc + 1 < gtotal) {
                    CP_WAIT0();
                    __syncthreads();
                    loadFrags((gc + 1) & 1, 0, aF[nxt], bF[nxt]);
                }
                #pragma unroll
                for (int mt = 0; mt < 4; mt++)
                    #pragma unroll
                    for (int nt = 0; nt < 8; nt++)
                        mma_tf32(acc[mt][nt], aF[pp][mt], bF[pp][nt]);
                pp ^= 1;
            }
        }

        int tl = start + it;
        int m0 = (tl >> 6) * 128, n0 = (tl & 63) * 256;
        #pragma unroll
        for (int mt = 0; mt < 4; mt++) {
            int m = m0 + wm * 64 + mt * 16 + r4;
            #pragma unroll
            for (int nt = 0; nt < 8; nt++) {
                int n = n0 + wn * 64 + nt * 8 + cs * 2;
                float2 bb = *(const float2*)(lat_bias + n);
                float2 v0 = make_float2(acc[mt][nt][0] + bb.x, acc[mt][nt][1] + bb.y);
                float2 v1 = make_float2(acc[mt][nt][2] + bb.x, acc[mt][nt][3] + bb.y);
                *(float2*)(C + (size_t)m * L_DIM + n) = v0;
                *(float2*)(C + (size_t)(m + 8) * L_DIM + n) = v1;
            }
        }
    }
}

// ============================ kernel 4: top-k (register-buffered single pass) ============================
__global__ void __launch_bounds__(256) topk_kernel(const float* __restrict__ P,
                                                   const float* __restrict__ lat_bias,
                                                   float* __restrict__ latents) {
    __shared__ float s_redf[8];
    __shared__ int   s_redi[8];
    __shared__ int   s_total;
    __shared__ float s_rms;
    __shared__ int   s_cnt, s_over;
    __shared__ int      cand_idx[CAND_CAP];
    __shared__ uint32_t srt_key[CAND_CAP];
    __shared__ int      srt_idx[CAND_CAP];
    __shared__ int      unc_ix[UNC_CAP];
    __shared__ float    unc_ex[UNC_CAP];
    __shared__ int      fin_idx[K_TOP];
    __shared__ float    fin_val[K_TOP];

    int row = blockIdx.x, t = threadIdx.x, lane = t & 31, wid = t >> 5;
    const float* Pr = P + (size_t)row * L_DIM;
    const float4* Pr4 = (const float4*)Pr;

    // ---- sample rms from iteration 0 (1024 values held in registers) ----
    float4 v0 = Pr4[t];
    float samp = v0.x * v0.x + v0.y * v0.y + v0.z * v0.z + v0.w * v0.w;
    for (int o = 16; o; o >>= 1) samp += __shfl_down_sync(0xFFFFFFFFu, samp, o);
    if (lane == 0) s_redf[wid] = samp;
    if (t == 0) { s_cnt = 0; s_over = 0; }
    __syncthreads();
    if (t == 0) {
        float a = 0.f;
        for (int w = 0; w < 8; w++) a += s_redf[w];
        s_rms = sqrtf(a / 1024.0f);
    }
    __syncthreads();
    float T = 2.28f * s_rms;

    // ---- single streaming pass: filter into per-thread hit buffer ----
    int lidx[HIT_CAP];
    int cnt = 0;
    #pragma unroll 4
    for (int i = 0; i < 16; i++) {
        int q = t + (i << 8);
        float4 v = (i == 0) ? v0 : Pr4[q];
        if (v.x > T) { if (cnt < HIT_CAP) lidx[cnt] = q * 4 + 0; cnt++; }
        if (v.y > T) { if (cnt < HIT_CAP) lidx[cnt] = q * 4 + 1; cnt++; }
        if (v.z > T) { if (cnt < HIT_CAP) lidx[cnt] = q * 4 + 2; cnt++; }
        if (v.w > T) { if (cnt < HIT_CAP) lidx[cnt] = q * 4 + 3; cnt++; }
    }
    {
        int stored = cnt < HIT_CAP ? cnt : HIT_CAP;
        if (cnt > HIT_CAP) atomicExch(&s_over, 1);
        int bs = 0;
        if (stored > 0) bs = atomicAdd(&s_cnt, stored);
        for (int j = 0; j < stored; j++)
            if (bs + j < CAND_CAP) cand_idx[bs + j] = lidx[j];
    }
    __syncthreads();
    int raw = s_cnt, over = s_over;
    __syncthreads();

    uint32_t klo = 0, khi = 0;
    int c = 0;
    bool have = (!over && raw >= K_TOP && raw <= CAND_CAP);

    for (int attempt = 0; attempt < 12; attempt++) {
        if (!have) {
            // fallback: ballot re-collect from gmem with current T (rare)
            if (raw < K_TOP && !over) T *= 0.93f;
            else if (raw > CAND_CAP || over) T *= 1.06f;
            if (t == 0) { s_cnt = 0; s_over = 0; }
            __syncthreads();
            for (int i = 0; i < 64; i++) {
                int idx = t + (i << 8);
                float v = Pr[idx];
                bool p = (v > T);
                unsigned m = __ballot_sync(0xFFFFFFFFu, p);
                if (m) {
                    int ldr = __ffs(m) - 1;
                    int bs = 0;
                    if (lane == ldr) bs = atomicAdd(&s_cnt, __popc(m));
                    bs = __shfl_sync(0xFFFFFFFFu, bs, ldr);
                    if (p) {
                        int slot = bs + __popc(m & ((1u << lane) - 1u));
                        if (slot < CAND_CAP) cand_idx[slot] = idx;
                    }
                }
            }
            __syncthreads();
            raw = s_cnt; over = 0;
            __syncthreads();
            if (raw < K_TOP || raw > CAND_CAP) { have = false; continue; }
            have = true;
        }
        c = raw < CAND_CAP ? raw : CAND_CAP;

        // fetch exact values; pad
        for (int j = t; j < CAND_CAP; j += 256) {
            if (j < c) {
                int idx = cand_idx[j];
                srt_key[j] = float_to_key(Pr[idx]);
                srt_idx[j] = idx;
            } else {
                srt_key[j] = 0u;
                srt_idx[j] = 0x7FFFFFFF;
            }
        }
        __syncthreads();

        // bitonic sort 512: (key desc, idx asc)
        for (int k2 = 2; k2 <= CAND_CAP; k2 <<= 1) {
            for (int j2 = k2 >> 1; j2 > 0; j2 >>= 1) {
                for (int i = t; i < CAND_CAP; i += 256) {
                    int ixj = i ^ j2;
                    if (ixj > i) {
                        uint32_t ki = srt_key[i], kj = srt_key[ixj];
                        int ii = srt_idx[i], ij = srt_idx[ixj];
                        bool gt = (ki > kj) || (ki == kj && ii < ij);
                        bool dir = ((i & k2) == 0);
                        if (dir ? !gt : gt) {
                            srt_key[i] = kj; srt_key[ixj] = ki;
                            srt_idx[i] = ij; srt_idx[ixj] = ii;
                        }
                    }
                }
                __syncthreads();
            }
        }

        float v100 = key_to_float(srt_key[K_TOP - 1]);
        klo = float_to_key(v100 - DELTA_BAND);
        khi = float_to_key(v100 + DELTA_BAND);
        if (v100 - DELTA_BAND >= T) break;     // candidate set covers the band
        T = (v100 - DELTA_BAND) * 0.999f;      // widen (rare) and redo collect
        have = false;
        raw = K_TOP;  // neutral so fallback doesn't shift T again
        over = 0;
        if (t == 0) { s_cnt = 0; }
        __syncthreads();
        // force fallback re-collect at new T
        {
            for (int i = 0; i < 64; i++) {
                int idx = t + (i << 8);
                float v = Pr[idx];
                bool p = (v > T);
                unsigned m = __ballot_sync(0xFFFFFFFFu, p);
                if (m) {
                    int ldr = __ffs(m) - 1;
                    int bs = 0;
                    if (lane == ldr) bs = atomicAdd(&s_cnt, __popc(m));
                    bs = __shfl_sync(0xFFFFFFFFu, bs, ldr);
                    if (p) {
                        int slot = bs + __popc(m & ((1u << lane) - 1u));
                        if (slot < CAND_CAP) cand_idx[slot] = idx;
                    }
                }
            }
            __syncthreads();
            raw = s_cnt;
            __syncthreads();
            have = (raw >= K_TOP && raw <= CAND_CAP);
        }
    }

    // ---- band boundaries ----
    {
        int l0 = 0, l1 = 0;
        for (int j = t; j < CAND_CAP; j += 256) {
            l0 += (int)(srt_key[j] > khi);
            l1 += (int)(srt_key[j] >= klo);
        }
        int v = l0;
        for (int o = 16; o; o >>= 1) v += __shfl_down_sync(0xFFFFFFFFu, v, o);
        if (lane == 0) s_redi[wid] = v;
        __syncthreads();
        if (t == 0) { int tot = 0; for (int w = 0; w < 8; w++) tot += s_redi[w]; s_total = tot; }
        __syncthreads();
        l0 = s_total;
        __syncthreads();
        v = l1;
        for (int o = 16; o; o >>= 1) v += __shfl_down_sync(0xFFFFFFFFu, v, o);
        if (lane == 0) s_redi[wid] = v;
        __syncthreads();
        if (t == 0) { int tot = 0; for (int w = 0; w < 8; w++) tot += s_redi[w]; s_total = tot; }
        __syncthreads();
        l1 = s_total;
        __syncthreads();
        if (t == 0) { s_redi[0] = l0; s_redi[1] = l1; }
        __syncthreads();
    }
    int j0 = s_redi[0];
    int j1 = s_redi[1];
    if (j0 > K_TOP - 1) j0 = K_TOP - 1;
    int U = j1 - j0; if (U > UNC_CAP) U = UNC_CAP;
    int need = K_TOP - j0;

    if (t < U) unc_ix[t] = srt_idx[j0 + t];
    __syncthreads();

    // ---- zero-fill the latents row (stores drain under the exact dots) ----
    {
        float4 z4 = make_float4(0.f, 0.f, 0.f, 0.f);
        float4* dst = (float4*)(latents + (size_t)row * L_DIM);
        #pragma unroll 4
        for (int i = 0; i < 16; i++) dst[t + (i << 8)] = z4;
    }

    // ---- exact recompute for band members ----
    const float* Xr = g_Xb + (size_t)row * D_DIM;
    for (int q = wid; q < U; q += 8) {
        const float* w = g_WT + (size_t)unc_ix[q] * D_DIM;
        float s = 0.f, comp = 0.f;
        for (int d = lane; d < D_DIM; d += 32) {
            float prod = Xr[d] * w[d];
            float tn = s + prod;
            if (fabsf(s) >= fabsf(prod)) comp += (s - tn) + prod;
            else                         comp += (prod - tn) + s;
            s = tn;
        }
        s += comp;
        for (int o = 16; o; o >>= 1) s += __shfl_xor_sync(0xFFFFFFFFu, s, o);
        if (lane == 0) unc_ex[q] = s + lat_bias[unc_ix[q]];
    }
    __syncthreads();

    if (t < j0) { fin_idx[t] = srt_idx[t]; fin_val[t] = key_to_float(srt_key[t]); }
    __syncthreads();
    if (t == 0) {
        for (int a = 1; a < U; a++) {
            float vv = unc_ex[a]; int ii = unc_ix[a]; int b = a - 1;
            while (b >= 0 && (unc_ex[b] < vv || (unc_ex[b] == vv && unc_ix[b] > ii))) {
                unc_ex[b + 1] = unc_ex[b]; unc_ix[b + 1] = unc_ix[b]; b--;
            }
            unc_ex[b + 1] = vv; unc_ix[b + 1] = ii;
        }
        for (int q = 0; q < need; q++) {
            fin_idx[j0 + q] = unc_ix[q]; fin_val[j0 + q] = unc_ex[q];
        }
    }
    __syncthreads();

    if (t < K_TOP) {
        int my = fin_idx[t]; float v = fin_val[t];
        int r = 0;
        for (int q = 0; q < K_TOP; q++) r += (int)(fin_idx[q] < my);
        g_tidx[row * K_TOP + r] = my;
        g_tval[row * K_TOP + r] = v;
        latents[(size_t)row * L_DIM + my] = v;
    }
}

// ============================ kernel 5: sparse decode ============================
__global__ void __launch_bounds__(256) decode_kernel(const float* __restrict__ Wd,
                                                     const float* __restrict__ pre_bias,
                                                     float* __restrict__ recons) {
    __shared__ int sidx[K_TOP];
    __shared__ float sval[K_TOP];
    int row = blockIdx.x, t = threadIdx.x;
    if (t < K_TOP) { sidx[t] = g_tidx[row * K_TOP + t]; sval[t] = g_tval[row * K_TOP + t]; }
    __syncthreads();
    float a0 = 0.f, a1 = 0.f, a2 = 0.f;
    #pragma unroll 4
    for (int j = 0; j < K_TOP; j++) {
        const float* w = Wd + (size_t)sidx[j] * D_DIM;
        float v = sval[j];
        a0 += v * __ldg(w + t);
        a1 += v * __ldg(w + t + 256);
        a2 += v * __ldg(w + t + 512);
    }
    float sd = g_std[row], mu = g_mu[row];
    float* Rr = recons + (size_t)row * D_DIM;
    Rr[t]       = (a0 + pre_bias[t])       * sd + mu;
    Rr[t + 256] = (a1 + pre_bias[t + 256]) * sd + mu;
    Rr[t + 512] = (a2 + pre_bias[t + 512]) * sd + mu;
}

// ============================ launch ============================
extern "C" void kernel_launch(void* const* d_in, const int* in_sizes, int n_in,
                              void* d_out, int out_size) {
    const float* x        = (const float*)d_in[0];
    const float* pre_bias = (const float*)d_in[1];
    const float* lat_bias = (const float*)d_in[2];
    const float* W_enc    = (const float*)d_in[3];
    const float* W_dec    = (const float*)d_in[4];

    float* outP = (float*)d_out;
    float* outL = outP + (size_t)B_DIM * L_DIM;
    float* outR = outL + (size_t)B_DIM * L_DIM;

    cudaFuncSetAttribute(gemm_kernel, cudaFuncAttributeMaxDynamicSharedMemorySize, GEMM_SMEM);

    prep_kernel<<<B_DIM + WP_BLOCKS, 256>>>(x, pre_bias, W_enc);
    gemm_kernel<<<GEMM_CTAS, 256, GEMM_SMEM>>>(lat_bias, outP);
    topk_kernel<<<B_DIM, 256>>>(outP, lat_bias, outL);
    decode_kernel<<<B_DIM, 256>>>(W_dec, pre_bias, outR);
}